// round 1
// baseline (speedup 1.0000x reference)
#include <cuda_runtime.h>
#include <cuda_bf16.h>
#include <math_constants.h>

// Problem constants
#define BATCH 4
#define SEQ   2048
#define DMODEL 1024
#define MROWS (BATCH * SEQ)          // 8192
#define SCALE (1.0f / 32.0f)         // 1/sqrt(1024)

// Scratch (allocation-free rule: __device__ globals)
__device__ float g_q[(size_t)MROWS * DMODEL];                 // 32 MB
__device__ float g_k[(size_t)MROWS * DMODEL];                 // 32 MB
__device__ float g_v[(size_t)MROWS * DMODEL];                 // 32 MB
__device__ float g_s[(size_t)BATCH * SEQ * SEQ];              // 64 MB

// ---------------------------------------------------------------------------
// Kernel 1: fused QKV projection.  C[z] = x @ W[z],  M=8192, N=1024, K=1024
// 128x128 block tile, BK=8, 256 threads, 8x8 per thread.
// ---------------------------------------------------------------------------
__global__ __launch_bounds__(256) void qkv_gemm_kernel(
    const float* __restrict__ x,
    const float* __restrict__ Wq,
    const float* __restrict__ Wk,
    const float* __restrict__ Wv)
{
    const int N = DMODEL, K = DMODEL;
    const float* __restrict__ W = (blockIdx.z == 0) ? Wq : (blockIdx.z == 1 ? Wk : Wv);
    float* __restrict__ C = (blockIdx.z == 0) ? g_q : (blockIdx.z == 1 ? g_k : g_v);

    const int m0 = blockIdx.y * 128;
    const int n0 = blockIdx.x * 128;

    __shared__ float As[8][128];
    __shared__ float Bs[8][128];

    const int tid = threadIdx.x;
    const int ar = tid >> 1;            // 0..127 row of A tile
    const int ac = (tid & 1) * 4;       // 0 or 4 within BK
    const int br = tid >> 5;            // 0..7 row of B tile (k)
    const int bc = (tid & 31) * 4;      // 0..124 col of B tile
    const int tx = tid & 15;
    const int ty = tid >> 4;

    float acc[8][8];
    #pragma unroll
    for (int i = 0; i < 8; ++i)
        #pragma unroll
        for (int j = 0; j < 8; ++j) acc[i][j] = 0.0f;

    for (int k0 = 0; k0 < K; k0 += 8) {
        float4 a4 = *(const float4*)(x + (size_t)(m0 + ar) * K + k0 + ac);
        As[ac + 0][ar] = a4.x;
        As[ac + 1][ar] = a4.y;
        As[ac + 2][ar] = a4.z;
        As[ac + 3][ar] = a4.w;
        *(float4*)&Bs[br][bc] = *(const float4*)(W + (size_t)(k0 + br) * N + n0 + bc);
        __syncthreads();

        #pragma unroll
        for (int kk = 0; kk < 8; ++kk) {
            float a[8], b[8];
            float4 t;
            t = *(const float4*)&As[kk][ty * 8];     a[0]=t.x; a[1]=t.y; a[2]=t.z; a[3]=t.w;
            t = *(const float4*)&As[kk][ty * 8 + 4]; a[4]=t.x; a[5]=t.y; a[6]=t.z; a[7]=t.w;
            t = *(const float4*)&Bs[kk][tx * 8];     b[0]=t.x; b[1]=t.y; b[2]=t.z; b[3]=t.w;
            t = *(const float4*)&Bs[kk][tx * 8 + 4]; b[4]=t.x; b[5]=t.y; b[6]=t.z; b[7]=t.w;
            #pragma unroll
            for (int i = 0; i < 8; ++i)
                #pragma unroll
                for (int j = 0; j < 8; ++j)
                    acc[i][j] = fmaf(a[i], b[j], acc[i][j]);
        }
        __syncthreads();
    }

    #pragma unroll
    for (int i = 0; i < 8; ++i) {
        float* cp = C + (size_t)(m0 + ty * 8 + i) * N + n0 + tx * 8;
        float4 v0 = make_float4(acc[i][0], acc[i][1], acc[i][2], acc[i][3]);
        float4 v1 = make_float4(acc[i][4], acc[i][5], acc[i][6], acc[i][7]);
        *(float4*)cp       = v0;
        *(float4*)(cp + 4) = v1;
    }
}

// ---------------------------------------------------------------------------
// Kernel 2: S = Q @ K^T (per batch).  M=N=2048, K=1024.  NT gemm.
// Skips fully-masked blocks (k-tile start > q-tile end).
// ---------------------------------------------------------------------------
__global__ __launch_bounds__(256) void score_gemm_kernel()
{
    if (blockIdx.x > blockIdx.y) return;   // whole block above diagonal

    const int b  = blockIdx.z;
    const int m0 = blockIdx.y * 128;       // query tile
    const int n0 = blockIdx.x * 128;       // key tile
    const int K  = DMODEL;

    const float* __restrict__ Q = g_q + (size_t)b * SEQ * DMODEL;
    const float* __restrict__ Km = g_k + (size_t)b * SEQ * DMODEL;
    float* __restrict__ S = g_s + (size_t)b * SEQ * SEQ;

    __shared__ float As[8][128];
    __shared__ float Bs[8][128];

    const int tid = threadIdx.x;
    const int ar = tid >> 1;
    const int ac = (tid & 1) * 4;
    const int tx = tid & 15;
    const int ty = tid >> 4;

    float acc[8][8];
    #pragma unroll
    for (int i = 0; i < 8; ++i)
        #pragma unroll
        for (int j = 0; j < 8; ++j) acc[i][j] = 0.0f;

    for (int k0 = 0; k0 < K; k0 += 8) {
        float4 a4 = *(const float4*)(Q + (size_t)(m0 + ar) * K + k0 + ac);
        As[ac + 0][ar] = a4.x;
        As[ac + 1][ar] = a4.y;
        As[ac + 2][ar] = a4.z;
        As[ac + 3][ar] = a4.w;
        // B tile: Bs[kk][n] = Kmat[(n0+n)*K + k0+kk]   (same transposed-load pattern)
        float4 b4 = *(const float4*)(Km + (size_t)(n0 + ar) * K + k0 + ac);
        Bs[ac + 0][ar] = b4.x;
        Bs[ac + 1][ar] = b4.y;
        Bs[ac + 2][ar] = b4.z;
        Bs[ac + 3][ar] = b4.w;
        __syncthreads();

        #pragma unroll
        for (int kk = 0; kk < 8; ++kk) {
            float a[8], bb[8];
            float4 t;
            t = *(const float4*)&As[kk][ty * 8];     a[0]=t.x; a[1]=t.y; a[2]=t.z; a[3]=t.w;
            t = *(const float4*)&As[kk][ty * 8 + 4]; a[4]=t.x; a[5]=t.y; a[6]=t.z; a[7]=t.w;
            t = *(const float4*)&Bs[kk][tx * 8];     bb[0]=t.x; bb[1]=t.y; bb[2]=t.z; bb[3]=t.w;
            t = *(const float4*)&Bs[kk][tx * 8 + 4]; bb[4]=t.x; bb[5]=t.y; bb[6]=t.z; bb[7]=t.w;
            #pragma unroll
            for (int i = 0; i < 8; ++i)
                #pragma unroll
                for (int j = 0; j < 8; ++j)
                    acc[i][j] = fmaf(a[i], bb[j], acc[i][j]);
        }
        __syncthreads();
    }

    #pragma unroll
    for (int i = 0; i < 8; ++i) {
        float* sp = S + (size_t)(m0 + ty * 8 + i) * SEQ + n0 + tx * 8;
        float4 v0 = make_float4(acc[i][0], acc[i][1], acc[i][2], acc[i][3]);
        float4 v1 = make_float4(acc[i][4], acc[i][5], acc[i][6], acc[i][7]);
        *(float4*)sp       = v0;
        *(float4*)(sp + 4) = v1;
    }
}

// ---------------------------------------------------------------------------
// Kernel 3: causal softmax in place over rows of S.
// One block (256 threads) per (batch, q) row.  Writes 0 above the diagonal.
// ---------------------------------------------------------------------------
__global__ __launch_bounds__(256) void softmax_kernel()
{
    const int row = blockIdx.x;            // 0..8191
    const int b = row >> 11;
    const int q = row & (SEQ - 1);
    float* __restrict__ S = g_s + (size_t)b * SEQ * SEQ + (size_t)q * SEQ;
    const int nvalid = q + 1;
    const int tid = threadIdx.x;

    __shared__ float red[256];

    // 1) max over valid entries (scaled)
    float lmax = -CUDART_INF_F;
    for (int j = tid; j < nvalid; j += 256)
        lmax = fmaxf(lmax, S[j] * SCALE);
    red[tid] = lmax;
    __syncthreads();
    for (int s = 128; s > 0; s >>= 1) {
        if (tid < s) red[tid] = fmaxf(red[tid], red[tid + s]);
        __syncthreads();
    }
    const float rmax = red[0];
    __syncthreads();

    // 2) exp + sum (store exp in place)
    float lsum = 0.0f;
    for (int j = tid; j < nvalid; j += 256) {
        float e = __expf(S[j] * SCALE - rmax);
        S[j] = e;
        lsum += e;
    }
    red[tid] = lsum;
    __syncthreads();
    for (int s = 128; s > 0; s >>= 1) {
        if (tid < s) red[tid] += red[tid + s];
        __syncthreads();
    }
    const float inv = 1.0f / red[0];

    // 3) normalize; zero the masked tail so PV is a plain GEMM
    for (int j = tid; j < SEQ; j += 256) {
        if (j < nvalid) S[j] *= inv;
        else            S[j] = 0.0f;
    }
}

// ---------------------------------------------------------------------------
// Kernel 4: O = P @ V (per batch).  M=2048, N=1024, K truncated at causal edge.
// ---------------------------------------------------------------------------
__global__ __launch_bounds__(256) void pv_gemm_kernel(float* __restrict__ out)
{
    const int b  = blockIdx.z;
    const int m0 = blockIdx.y * 128;
    const int n0 = blockIdx.x * 128;
    const int N  = DMODEL;
    const int Kmax = m0 + 128;             // P is zero beyond the diagonal

    const float* __restrict__ P = g_s + (size_t)b * SEQ * SEQ;
    const float* __restrict__ V = g_v + (size_t)b * SEQ * DMODEL;
    float* __restrict__ C = out + (size_t)b * SEQ * DMODEL;

    __shared__ float As[8][128];
    __shared__ float Bs[8][128];

    const int tid = threadIdx.x;
    const int ar = tid >> 1;
    const int ac = (tid & 1) * 4;
    const int br = tid >> 5;
    const int bc = (tid & 31) * 4;
    const int tx = tid & 15;
    const int ty = tid >> 4;

    float acc[8][8];
    #pragma unroll
    for (int i = 0; i < 8; ++i)
        #pragma unroll
        for (int j = 0; j < 8; ++j) acc[i][j] = 0.0f;

    for (int k0 = 0; k0 < Kmax; k0 += 8) {
        float4 a4 = *(const float4*)(P + (size_t)(m0 + ar) * SEQ + k0 + ac);
        As[ac + 0][ar] = a4.x;
        As[ac + 1][ar] = a4.y;
        As[ac + 2][ar] = a4.z;
        As[ac + 3][ar] = a4.w;
        *(float4*)&Bs[br][bc] = *(const float4*)(V + (size_t)(k0 + br) * N + n0 + bc);
        __syncthreads();

        #pragma unroll
        for (int kk = 0; kk < 8; ++kk) {
            float a[8], bb[8];
            float4 t;
            t = *(const float4*)&As[kk][ty * 8];     a[0]=t.x; a[1]=t.y; a[2]=t.z; a[3]=t.w;
            t = *(const float4*)&As[kk][ty * 8 + 4]; a[4]=t.x; a[5]=t.y; a[6]=t.z; a[7]=t.w;
            t = *(const float4*)&Bs[kk][tx * 8];     bb[0]=t.x; bb[1]=t.y; bb[2]=t.z; bb[3]=t.w;
            t = *(const float4*)&Bs[kk][tx * 8 + 4]; bb[4]=t.x; bb[5]=t.y; bb[6]=t.z; bb[7]=t.w;
            #pragma unroll
            for (int i = 0; i < 8; ++i)
                #pragma unroll
                for (int j = 0; j < 8; ++j)
                    acc[i][j] = fmaf(a[i], bb[j], acc[i][j]);
        }
        __syncthreads();
    }

    #pragma unroll
    for (int i = 0; i < 8; ++i) {
        float* cp = C + (size_t)(m0 + ty * 8 + i) * N + n0 + tx * 8;
        float4 v0 = make_float4(acc[i][0], acc[i][1], acc[i][2], acc[i][3]);
        float4 v1 = make_float4(acc[i][4], acc[i][5], acc[i][6], acc[i][7]);
        *(float4*)cp       = v0;
        *(float4*)(cp + 4) = v1;
    }
}

// ---------------------------------------------------------------------------
extern "C" void kernel_launch(void* const* d_in, const int* in_sizes, int n_in,
                              void* d_out, int out_size)
{
    (void)in_sizes; (void)n_in; (void)out_size;
    const float* x  = (const float*)d_in[0];
    const float* Wq = (const float*)d_in[1];
    const float* Wk = (const float*)d_in[2];
    const float* Wv = (const float*)d_in[3];
    float* out = (float*)d_out;

    dim3 gQKV(DMODEL / 128, MROWS / 128, 3);       // 8 x 64 x 3
    qkv_gemm_kernel<<<gQKV, 256>>>(x, Wq, Wk, Wv);

    dim3 gS(SEQ / 128, SEQ / 128, BATCH);          // 16 x 16 x 4
    score_gemm_kernel<<<gS, 256>>>();

    softmax_kernel<<<BATCH * SEQ, 256>>>();

    dim3 gPV(DMODEL / 128, SEQ / 128, BATCH);      // 8 x 16 x 4
    pv_gemm_kernel<<<gPV, 256>>>(out);
}

// round 4
// speedup vs baseline: 3.5521x; 3.5521x over previous
#include <cuda_runtime.h>
#include <cstdint>
#include <math_constants.h>

#define BATCH 4
#define SEQ   2048
#define DM    1024
#define MROWS (BATCH * SEQ)
#define SCALE (1.0f / 32.0f)

// GEMM tiling
#define BM 128
#define BN 128
#define BK 32
#define LDS_T 36                     // 32 + 4 pad (floats)
#define TILE_F (BM * LDS_T)          // 4608 floats per tile buffer
#define SM_A0 0
#define SM_B0 (TILE_F)
#define SM_A1 (2 * TILE_F)
#define SM_B1 (3 * TILE_F)
#define SMEM_BYTES (4 * TILE_F * 4)  // 73728 B

// Scratch (__device__ globals; allocation-free rule)
__device__ float g_xr[(size_t)MROWS * DM];          // x  (tf32-rounded)
__device__ float g_wt[(size_t)3 * DM * DM];         // W^T (tf32-rounded)
__device__ float g_q [(size_t)MROWS * DM];          // q  (tf32-rounded)
__device__ float g_k [(size_t)MROWS * DM];          // k  (tf32-rounded)
__device__ float g_vt[(size_t)MROWS * DM];          // V^T per batch [b][d][key], tf32
__device__ float g_s [(size_t)BATCH * SEQ * SEQ];   // scores / probs

// ---------------------------------------------------------------------------
__device__ __forceinline__ float tf32r(float x) {
    uint32_t u;
    asm("cvt.rna.tf32.f32 %0, %1;" : "=r"(u) : "f"(x));
    return __uint_as_float(u);
}

__device__ __forceinline__ void cp16(uint32_t dst, const void* src) {
    asm volatile("cp.async.cg.shared.global [%0], [%1], 16;"
                 :: "r"(dst), "l"(src) : "memory");
}

__device__ __forceinline__ void mma8(float* c, const uint32_t* a, const uint32_t* b) {
    asm volatile(
        "mma.sync.aligned.m16n8k8.row.col.f32.tf32.tf32.f32 "
        "{%0,%1,%2,%3}, {%4,%5,%6,%7}, {%8,%9}, {%0,%1,%2,%3};"
        : "+f"(c[0]), "+f"(c[1]), "+f"(c[2]), "+f"(c[3])
        : "r"(a[0]), "r"(a[1]), "r"(a[2]), "r"(a[3]), "r"(b[0]), "r"(b[1]));
}

// Issue cp.async for a 128x32-float K-major tile into padded SMEM.
__device__ __forceinline__ void load_tile(uint32_t smbase_b, const float* __restrict__ src,
                                          long ld, int tid) {
    #pragma unroll
    for (int i = 0; i < 4; ++i) {
        int idx = i * 256 + tid;
        int row = idx >> 3, c4 = idx & 7;
        cp16(smbase_b + (uint32_t)(row * LDS_T + c4 * 4) * 4,
             src + (size_t)row * ld + c4 * 4);
    }
}

// ---------------------------------------------------------------------------
// NT GEMM mainloop: C(128x128) += A(128xK, K-major) * B(128xK, K-major)^T
// Accumulators in c[2][8][4] per thread. Double-buffered cp.async.
// ---------------------------------------------------------------------------
__device__ __forceinline__ void gemm_tc(float* sm,
                                        const float* __restrict__ A, long lda,
                                        const float* __restrict__ B, long ldb,
                                        int nchunks, float c[2][8][4]) {
    const int tid = threadIdx.x, wid = tid >> 5, lane = tid & 31;
    const int warpM = wid & 3, warpN = wid >> 2;
    const int lr = lane >> 2, lc = lane & 3;
    const uint32_t smu = (uint32_t)__cvta_generic_to_shared(sm);

    load_tile(smu + SM_A0 * 4, A, lda, tid);
    load_tile(smu + SM_B0 * 4, B, ldb, tid);
    asm volatile("cp.async.commit_group;" ::: "memory");

    for (int i = 0; i < nchunks; ++i) {
        if (i + 1 < nchunks) {
            const uint32_t aoff = ((i + 1) & 1) ? SM_A1 : SM_A0;
            const uint32_t boff = ((i + 1) & 1) ? SM_B1 : SM_B0;
            load_tile(smu + aoff * 4, A + (size_t)(i + 1) * BK, lda, tid);
            load_tile(smu + boff * 4, B + (size_t)(i + 1) * BK, ldb, tid);
            asm volatile("cp.async.commit_group;" ::: "memory");
            asm volatile("cp.async.wait_group 1;" ::: "memory");
        } else {
            asm volatile("cp.async.wait_group 0;" ::: "memory");
        }
        __syncthreads();

        const float* a_sm = sm + ((i & 1) ? SM_A1 : SM_A0);
        const float* b_sm = sm + ((i & 1) ? SM_B1 : SM_B0);

        #pragma unroll
        for (int ks = 0; ks < 4; ++ks) {
            uint32_t a[2][4], b[8][2];
            #pragma unroll
            for (int t = 0; t < 2; ++t) {
                const int r = warpM * 32 + t * 16 + lr;
                const int k = ks * 8 + lc;
                a[t][0] = __float_as_uint(a_sm[r * LDS_T + k]);
                a[t][1] = __float_as_uint(a_sm[(r + 8) * LDS_T + k]);
                a[t][2] = __float_as_uint(a_sm[r * LDS_T + k + 4]);
                a[t][3] = __float_as_uint(a_sm[(r + 8) * LDS_T + k + 4]);
            }
            #pragma unroll
            for (int u = 0; u < 8; ++u) {
                const int n = warpN * 64 + u * 8 + lr;
                const int k = ks * 8 + lc;
                b[u][0] = __float_as_uint(b_sm[n * LDS_T + k]);
                b[u][1] = __float_as_uint(b_sm[n * LDS_T + k + 4]);
            }
            #pragma unroll
            for (int t = 0; t < 2; ++t)
                #pragma unroll
                for (int u = 0; u < 8; ++u)
                    mma8(c[t][u], a[t], b[u]);
        }
        __syncthreads();
    }
}

__device__ __forceinline__ void zero_c(float c[2][8][4]) {
    #pragma unroll
    for (int t = 0; t < 2; ++t)
        #pragma unroll
        for (int u = 0; u < 8; ++u)
            #pragma unroll
            for (int j = 0; j < 4; ++j) c[t][u][j] = 0.0f;
}

// Row-major epilogue (optional tf32 rounding).
__device__ __forceinline__ void epi_store(float c[2][8][4], float* __restrict__ C,
                                          long ldc, bool rnd) {
    const int tid = threadIdx.x, wid = tid >> 5, lane = tid & 31;
    const int warpM = wid & 3, warpN = wid >> 2;
    const int lr = lane >> 2, lc = lane & 3;
    #pragma unroll
    for (int t = 0; t < 2; ++t)
        #pragma unroll
        for (int u = 0; u < 8; ++u) {
            const int r = warpM * 32 + t * 16 + lr;
            const int n = warpN * 64 + u * 8 + lc * 2;
            float2 v0 = make_float2(c[t][u][0], c[t][u][1]);
            float2 v1 = make_float2(c[t][u][2], c[t][u][3]);
            if (rnd) {
                v0.x = tf32r(v0.x); v0.y = tf32r(v0.y);
                v1.x = tf32r(v1.x); v1.y = tf32r(v1.y);
            }
            *(float2*)&C[(size_t)r * ldc + n]       = v0;
            *(float2*)&C[(size_t)(r + 8) * ldc + n] = v1;
        }
}

// Transposed epilogue: Ct[n][m], tf32-rounded (for V^T).
__device__ __forceinline__ void epi_store_T(float c[2][8][4], float* __restrict__ Ct,
                                            long ldm) {
    const int tid = threadIdx.x, wid = tid >> 5, lane = tid & 31;
    const int warpM = wid & 3, warpN = wid >> 2;
    const int lr = lane >> 2, lc = lane & 3;
    #pragma unroll
    for (int t = 0; t < 2; ++t)
        #pragma unroll
        for (int u = 0; u < 8; ++u) {
            const int r = warpM * 32 + t * 16 + lr;
            const int n = warpN * 64 + u * 8 + lc * 2;
            Ct[(size_t)n * ldm + r]           = tf32r(c[t][u][0]);
            Ct[(size_t)(n + 1) * ldm + r]     = tf32r(c[t][u][1]);
            Ct[(size_t)n * ldm + r + 8]       = tf32r(c[t][u][2]);
            Ct[(size_t)(n + 1) * ldm + r + 8] = tf32r(c[t][u][3]);
        }
}

// ---------------------------------------------------------------------------
// Pre-pass kernels
// ---------------------------------------------------------------------------
__global__ __launch_bounds__(256) void roundx_kernel(const float* __restrict__ x) {
    size_t i = (size_t)blockIdx.x * blockDim.x + threadIdx.x;
    float4 v = ((const float4*)x)[i];
    v.x = tf32r(v.x); v.y = tf32r(v.y); v.z = tf32r(v.z); v.w = tf32r(v.w);
    ((float4*)g_xr)[i] = v;
}

__global__ __launch_bounds__(256) void wtrans_kernel(const float* __restrict__ Wq,
                                                     const float* __restrict__ Wk,
                                                     const float* __restrict__ Wv) {
    __shared__ float t[32][33];
    const int z = blockIdx.z;
    const float* __restrict__ W = (z == 0) ? Wq : (z == 1 ? Wk : Wv);
    float* __restrict__ O = g_wt + (size_t)z * DM * DM;
    const int tx = threadIdx.x, ty = threadIdx.y;
    const int n = blockIdx.x * 32 + tx;
    const int k0 = blockIdx.y * 32;
    for (int i = ty; i < 32; i += 8) t[i][tx] = W[(size_t)(k0 + i) * DM + n];
    __syncthreads();
    const int ko = blockIdx.y * 32 + tx;
    const int n0 = blockIdx.x * 32;
    for (int i = ty; i < 32; i += 8)
        O[(size_t)(n0 + i) * DM + ko] = tf32r(t[tx][i]);
}

// ---------------------------------------------------------------------------
// GEMM 1: QKV projection (NT with B = W^T).  z: 0=q, 1=k, 2=v(->V^T)
// ---------------------------------------------------------------------------
__global__ __launch_bounds__(256) void qkv_tc_kernel() {
    extern __shared__ float sm[];
    const int z = blockIdx.z;
    const long m0 = (long)blockIdx.y * BM;
    const long n0 = (long)blockIdx.x * BN;
    const float* A = g_xr + (size_t)m0 * DM;
    const float* B = g_wt + (size_t)z * DM * DM + (size_t)n0 * DM;

    float c[2][8][4];
    zero_c(c);
    gemm_tc(sm, A, DM, B, DM, DM / BK, c);

    if (z < 2) {
        float* C = (z == 0 ? g_q : g_k) + (size_t)m0 * DM + n0;
        epi_store(c, C, DM, true);
    } else {
        const int b = (int)(m0 / SEQ);
        const long mloc = m0 - (long)b * SEQ;
        float* Ct = g_vt + ((size_t)b * DM + n0) * SEQ + mloc;
        epi_store_T(c, Ct, SEQ);
    }
}

// ---------------------------------------------------------------------------
// GEMM 2: S = Q @ K^T per batch (NT), skipping above-diagonal tiles.
// ---------------------------------------------------------------------------
__global__ __launch_bounds__(256) void score_tc_kernel() {
    if (blockIdx.x > blockIdx.y) return;
    extern __shared__ float sm[];
    const int b = blockIdx.z;
    const long m0 = (long)blockIdx.y * BM;
    const long n0 = (long)blockIdx.x * BN;
    const float* A = g_q + ((size_t)b * SEQ + m0) * DM;
    const float* B = g_k + ((size_t)b * SEQ + n0) * DM;

    float c[2][8][4];
    zero_c(c);
    gemm_tc(sm, A, DM, B, DM, DM / BK, c);

    float* C = g_s + ((size_t)b * SEQ + m0) * SEQ + n0;
    epi_store(c, C, SEQ, false);
}

// ---------------------------------------------------------------------------
// Softmax (causal, in place). Rounds P to tf32; zeroes to 128-tile boundary.
// ---------------------------------------------------------------------------
__global__ __launch_bounds__(256) void softmax_kernel() {
    const int row = blockIdx.x;
    const int b = row >> 11;
    const int q = row & (SEQ - 1);
    float* __restrict__ S = g_s + (size_t)b * SEQ * SEQ + (size_t)q * SEQ;
    const int nvalid = q + 1;
    const int nzero = ((q >> 7) + 1) << 7;
    const int tid = threadIdx.x;

    __shared__ float red[256];

    float lmax = -CUDART_INF_F;
    for (int j = tid; j < nvalid; j += 256) lmax = fmaxf(lmax, S[j] * SCALE);
    red[tid] = lmax;
    __syncthreads();
    for (int s = 128; s > 0; s >>= 1) {
        if (tid < s) red[tid] = fmaxf(red[tid], red[tid + s]);
        __syncthreads();
    }
    const float rmax = red[0];
    __syncthreads();

    float lsum = 0.0f;
    for (int j = tid; j < nvalid; j += 256) {
        float e = __expf(S[j] * SCALE - rmax);
        S[j] = e;
        lsum += e;
    }
    red[tid] = lsum;
    __syncthreads();
    for (int s = 128; s > 0; s >>= 1) {
        if (tid < s) red[tid] += red[tid + s];
        __syncthreads();
    }
    const float inv = 1.0f / red[0];

    for (int j = tid; j < nzero; j += 256)
        S[j] = (j < nvalid) ? tf32r(S[j] * inv) : 0.0f;
}

// ---------------------------------------------------------------------------
// GEMM 3: O = P @ V  (A = P, B = V^T, NT), K truncated at causal edge.
// ---------------------------------------------------------------------------
__global__ __launch_bounds__(256) void pv_tc_kernel(float* __restrict__ out) {
    extern __shared__ float sm[];
    const int b = blockIdx.z;
    const long m0 = (long)blockIdx.y * BM;
    const long n0 = (long)blockIdx.x * BN;
    const float* A = g_s + ((size_t)b * SEQ + m0) * SEQ;
    const float* B = g_vt + ((size_t)b * DM + n0) * SEQ;
    const int nchunks = (int)((m0 + BM) / BK);

    float c[2][8][4];
    zero_c(c);
    gemm_tc(sm, A, SEQ, B, SEQ, nchunks, c);

    float* C = out + ((size_t)b * SEQ + m0) * DM + n0;
    epi_store(c, C, DM, false);
}

// ---------------------------------------------------------------------------
extern "C" void kernel_launch(void* const* d_in, const int* in_sizes, int n_in,
                              void* d_out, int out_size) {
    (void)in_sizes; (void)n_in; (void)out_size;
    const float* x  = (const float*)d_in[0];
    const float* Wq = (const float*)d_in[1];
    const float* Wk = (const float*)d_in[2];
    const float* Wv = (const float*)d_in[3];
    float* out = (float*)d_out;

    static bool attr_done = false;
    if (!attr_done) {
        cudaFuncSetAttribute(qkv_tc_kernel,   cudaFuncAttributeMaxDynamicSharedMemorySize, SMEM_BYTES);
        cudaFuncSetAttribute(score_tc_kernel, cudaFuncAttributeMaxDynamicSharedMemorySize, SMEM_BYTES);
        cudaFuncSetAttribute(pv_tc_kernel,    cudaFuncAttributeMaxDynamicSharedMemorySize, SMEM_BYTES);
        attr_done = true;
    }

    roundx_kernel<<<(MROWS * DM / 4) / 256, 256>>>(x);
    {
        dim3 g(DM / 32, DM / 32, 3);
        dim3 blk(32, 8);
        wtrans_kernel<<<g, blk>>>(Wq, Wk, Wv);
    }
    {
        dim3 g(DM / BN, MROWS / BM, 3);              // 8 x 64 x 3
        qkv_tc_kernel<<<g, 256, SMEM_BYTES>>>();
    }
    {
        dim3 g(SEQ / BN, SEQ / BM, BATCH);           // 16 x 16 x 4
        score_tc_kernel<<<g, 256, SMEM_BYTES>>>();
    }
    softmax_kernel<<<BATCH * SEQ, 256>>>();
    {
        dim3 g(DM / BN, SEQ / BM, BATCH);            // 8 x 16 x 4
        pv_tc_kernel<<<g, 256, SMEM_BYTES>>>(out);
    }
}

// round 6
// speedup vs baseline: 3.7108x; 1.0447x over previous
#include <cuda_runtime.h>
#include <cstdint>
#include <math_constants.h>

#define BATCH 4
#define SEQ   2048
#define DM    1024
#define MROWS (BATCH * SEQ)
#define SCALE (1.0f / 32.0f)

// GEMM tiling
#define BM 128
#define BN 128
#define BK 32
#define LDS_T 36                     // 32 + 4 pad (floats)
#define TILE_F (BM * LDS_T)          // 4608 floats per tile
#define STG_F  (2 * TILE_F)          // A+B per stage
#define SMEM_BYTES (3 * STG_F * 4)   // 110592 B (3 stages)

// Scratch (__device__ globals; allocation-free rule)
__device__ float g_xr[(size_t)MROWS * DM];          // x  (tf32-rounded)
__device__ float g_wt[(size_t)3 * DM * DM];         // W^T (tf32-rounded)
__device__ float g_q [(size_t)MROWS * DM];          // q  (tf32-rounded)
__device__ float g_k [(size_t)MROWS * DM];          // k  (tf32-rounded)
__device__ float g_vt[(size_t)MROWS * DM];          // V^T per batch [b][d][key], tf32
__device__ float g_s [(size_t)BATCH * SEQ * SEQ];   // scores / probs

// ---------------------------------------------------------------------------
__device__ __forceinline__ float tf32r(float x) {
    uint32_t u;
    asm("cvt.rna.tf32.f32 %0, %1;" : "=r"(u) : "f"(x));
    return __uint_as_float(u);
}

__device__ __forceinline__ void cp16(uint32_t dst, const void* src) {
    asm volatile("cp.async.cg.shared.global [%0], [%1], 16;"
                 :: "r"(dst), "l"(src) : "memory");
}

__device__ __forceinline__ void mma8(float* c, const uint32_t* a, const uint32_t* b) {
    asm volatile(
        "mma.sync.aligned.m16n8k8.row.col.f32.tf32.tf32.f32 "
        "{%0,%1,%2,%3}, {%4,%5,%6,%7}, {%8,%9}, {%0,%1,%2,%3};"
        : "+f"(c[0]), "+f"(c[1]), "+f"(c[2]), "+f"(c[3])
        : "r"(a[0]), "r"(a[1]), "r"(a[2]), "r"(a[3]), "r"(b[0]), "r"(b[1]));
}

// Issue cp.async for a 128x32-float K-major tile into padded SMEM.
__device__ __forceinline__ void load_tile(uint32_t smbase_b, const float* __restrict__ src,
                                          long ld, int tid) {
    #pragma unroll
    for (int i = 0; i < 4; ++i) {
        int idx = i * 256 + tid;
        int row = idx >> 3, c4 = idx & 7;
        cp16(smbase_b + (uint32_t)(row * LDS_T + c4 * 4) * 4,
             src + (size_t)row * ld + c4 * 4);
    }
}

// Load one ks-step of fragments (8 a-regs, 16 b-regs).
__device__ __forceinline__ void load_frags(const float* __restrict__ a_sm,
                                           const float* __restrict__ b_sm,
                                           int ks, int warpM, int warpN,
                                           int lr, int lc,
                                           uint32_t* a, uint32_t* b) {
    const int k = ks * 8 + lc;
    #pragma unroll
    for (int t = 0; t < 2; ++t) {
        const int r = warpM * 32 + t * 16 + lr;
        a[t * 4 + 0] = __float_as_uint(a_sm[r * LDS_T + k]);
        a[t * 4 + 1] = __float_as_uint(a_sm[(r + 8) * LDS_T + k]);
        a[t * 4 + 2] = __float_as_uint(a_sm[r * LDS_T + k + 4]);
        a[t * 4 + 3] = __float_as_uint(a_sm[(r + 8) * LDS_T + k + 4]);
    }
    #pragma unroll
    for (int u = 0; u < 8; ++u) {
        const int n = warpN * 64 + u * 8 + lr;
        b[u * 2 + 0] = __float_as_uint(b_sm[n * LDS_T + k]);
        b[u * 2 + 1] = __float_as_uint(b_sm[n * LDS_T + k + 4]);
    }
}

// ---------------------------------------------------------------------------
// NT GEMM mainloop: C(128x128) += A(128xK) * B(128xK)^T, both K-major.
// 3-stage cp.async pipeline, 1 barrier/chunk, ks-level register pipelining.
// ---------------------------------------------------------------------------
__device__ __forceinline__ void gemm_tc(float* sm,
                                        const float* __restrict__ A, long lda,
                                        const float* __restrict__ B, long ldb,
                                        int nchunks, float c[2][8][4]) {
    const int tid = threadIdx.x, wid = tid >> 5, lane = tid & 31;
    const int warpM = wid & 3, warpN = wid >> 2;
    const int lr = lane >> 2, lc = lane & 3;
    const uint32_t smu = (uint32_t)__cvta_generic_to_shared(sm);

    load_tile(smu, A, lda, tid);
    load_tile(smu + TILE_F * 4, B, ldb, tid);
    asm volatile("cp.async.commit_group;" ::: "memory");
    if (nchunks > 1) {
        load_tile(smu + STG_F * 4, A + BK, lda, tid);
        load_tile(smu + STG_F * 4 + TILE_F * 4, B + BK, ldb, tid);
    }
    asm volatile("cp.async.commit_group;" ::: "memory");

    for (int i = 0; i < nchunks; ++i) {
        if (i + 1 < nchunks)
            asm volatile("cp.async.wait_group 1;" ::: "memory");
        else
            asm volatile("cp.async.wait_group 0;" ::: "memory");
        __syncthreads();

        if (i + 2 < nchunks) {
            const int s = (i + 2) % 3;
            load_tile(smu + (uint32_t)s * STG_F * 4,
                      A + (size_t)(i + 2) * BK, lda, tid);
            load_tile(smu + (uint32_t)s * STG_F * 4 + TILE_F * 4,
                      B + (size_t)(i + 2) * BK, ldb, tid);
        }
        asm volatile("cp.async.commit_group;" ::: "memory");

        const float* a_sm = sm + (i % 3) * STG_F;
        const float* b_sm = a_sm + TILE_F;

        uint32_t aA[8], bA[16], aB[8], bB[16];
        load_frags(a_sm, b_sm, 0, warpM, warpN, lr, lc, aA, bA);
        #pragma unroll
        for (int ks = 0; ks < 4; ++ks) {
            if (ks < 3)
                load_frags(a_sm, b_sm, ks + 1, warpM, warpN, lr, lc,
                           (ks & 1) ? aA : aB, (ks & 1) ? bA : bB);
            const uint32_t* a = (ks & 1) ? aB : aA;
            const uint32_t* b = (ks & 1) ? bB : bA;
            #pragma unroll
            for (int t = 0; t < 2; ++t)
                #pragma unroll
                for (int u = 0; u < 8; ++u)
                    mma8(c[t][u], a + t * 4, b + u * 2);
        }
    }
}

__device__ __forceinline__ void zero_c(float c[2][8][4]) {
    #pragma unroll
    for (int t = 0; t < 2; ++t)
        #pragma unroll
        for (int u = 0; u < 8; ++u)
            #pragma unroll
            for (int j = 0; j < 4; ++j) c[t][u][j] = 0.0f;
}

// Row-major epilogue (optional tf32 rounding).
__device__ __forceinline__ void epi_store(float c[2][8][4], float* __restrict__ C,
                                          long ldc, bool rnd) {
    const int tid = threadIdx.x, wid = tid >> 5, lane = tid & 31;
    const int warpM = wid & 3, warpN = wid >> 2;
    const int lr = lane >> 2, lc = lane & 3;
    #pragma unroll
    for (int t = 0; t < 2; ++t)
        #pragma unroll
        for (int u = 0; u < 8; ++u) {
            const int r = warpM * 32 + t * 16 + lr;
            const int n = warpN * 64 + u * 8 + lc * 2;
            float2 v0 = make_float2(c[t][u][0], c[t][u][1]);
            float2 v1 = make_float2(c[t][u][2], c[t][u][3]);
            if (rnd) {
                v0.x = tf32r(v0.x); v0.y = tf32r(v0.y);
                v1.x = tf32r(v1.x); v1.y = tf32r(v1.y);
            }
            *(float2*)&C[(size_t)r * ldc + n]       = v0;
            *(float2*)&C[(size_t)(r + 8) * ldc + n] = v1;
        }
}

// Transposed epilogue: Ct[n][m], tf32-rounded (for V^T).
__device__ __forceinline__ void epi_store_T(float c[2][8][4], float* __restrict__ Ct,
                                            long ldm) {
    const int tid = threadIdx.x, wid = tid >> 5, lane = tid & 31;
    const int warpM = wid & 3, warpN = wid >> 2;
    const int lr = lane >> 2, lc = lane & 3;
    #pragma unroll
    for (int t = 0; t < 2; ++t)
        #pragma unroll
        for (int u = 0; u < 8; ++u) {
            const int r = warpM * 32 + t * 16 + lr;
            const int n = warpN * 64 + u * 8 + lc * 2;
            Ct[(size_t)n * ldm + r]           = tf32r(c[t][u][0]);
            Ct[(size_t)(n + 1) * ldm + r]     = tf32r(c[t][u][1]);
            Ct[(size_t)n * ldm + r + 8]       = tf32r(c[t][u][2]);
            Ct[(size_t)(n + 1) * ldm + r + 8] = tf32r(c[t][u][3]);
        }
}

// ---------------------------------------------------------------------------
// Pre-pass kernels
// ---------------------------------------------------------------------------
__global__ __launch_bounds__(256) void roundx_kernel(const float* __restrict__ x) {
    size_t i = (size_t)blockIdx.x * blockDim.x + threadIdx.x;
    float4 v = ((const float4*)x)[i];
    v.x = tf32r(v.x); v.y = tf32r(v.y); v.z = tf32r(v.z); v.w = tf32r(v.w);
    ((float4*)g_xr)[i] = v;
}

__global__ __launch_bounds__(256) void wtrans_kernel(const float* __restrict__ Wq,
                                                     const float* __restrict__ Wk,
                                                     const float* __restrict__ Wv) {
    __shared__ float t[32][33];
    const int z = blockIdx.z;
    const float* __restrict__ W = (z == 0) ? Wq : (z == 1 ? Wk : Wv);
    float* __restrict__ O = g_wt + (size_t)z * DM * DM;
    const int tx = threadIdx.x, ty = threadIdx.y;
    const int n = blockIdx.x * 32 + tx;
    const int k0 = blockIdx.y * 32;
    for (int i = ty; i < 32; i += 8) t[i][tx] = W[(size_t)(k0 + i) * DM + n];
    __syncthreads();
    const int ko = blockIdx.y * 32 + tx;
    const int n0 = blockIdx.x * 32;
    for (int i = ty; i < 32; i += 8)
        O[(size_t)(n0 + i) * DM + ko] = tf32r(t[tx][i]);
}

// ---------------------------------------------------------------------------
// GEMM 1: Q and K projections only (z: 0=q, 1=k).
// ---------------------------------------------------------------------------
__global__ __launch_bounds__(256, 2) void qkv_qk_kernel() {
    extern __shared__ float sm[];
    const int z = blockIdx.z;
    const long m0 = (long)blockIdx.y * BM;
    const long n0 = (long)blockIdx.x * BN;
    const float* A = g_xr + (size_t)m0 * DM;
    const float* B = g_wt + (size_t)z * DM * DM + (size_t)n0 * DM;

    float c[2][8][4];
    zero_c(c);
    gemm_tc(sm, A, DM, B, DM, DM / BK, c);

    float* C = (z == 0 ? g_q : g_k) + (size_t)m0 * DM + n0;
    epi_store(c, C, DM, true);
}

// ---------------------------------------------------------------------------
// GEMM 2 (merged): ids [0,544): S = Q@K^T lower-tri tiles.
//                  ids [544,1056): V-projection -> V^T (independent work).
// ---------------------------------------------------------------------------
__global__ __launch_bounds__(256, 2) void scorev_kernel() {
    extern __shared__ float sm[];
    const int id = blockIdx.x;
    float c[2][8][4];
    zero_c(c);

    if (id < 544) {
        const int b = id / 136;
        const int tt = id - b * 136;
        int by = (int)((sqrtf(8.0f * tt + 1.0f) - 1.0f) * 0.5f);
        while ((by + 1) * (by + 2) / 2 <= tt) ++by;
        while (by * (by + 1) / 2 > tt) --by;
        const int bx = tt - by * (by + 1) / 2;

        const long m0 = (long)by * BM;
        const long n0 = (long)bx * BN;
        const float* A = g_q + ((size_t)b * SEQ + m0) * DM;
        const float* B = g_k + ((size_t)b * SEQ + n0) * DM;

        gemm_tc(sm, A, DM, B, DM, DM / BK, c);

        float* C = g_s + ((size_t)b * SEQ + m0) * SEQ + n0;
        epi_store(c, C, SEQ, false);
    } else {
        const int r = id - 544;
        const long n0 = (long)(r & 7) * BN;
        const long m0 = (long)(r >> 3) * BM;
        const float* A = g_xr + (size_t)m0 * DM;
        const float* B = g_wt + (size_t)2 * DM * DM + (size_t)n0 * DM;

        gemm_tc(sm, A, DM, B, DM, DM / BK, c);

        const int b = (int)(m0 / SEQ);
        const long mloc = m0 - (long)b * SEQ;
        float* Ct = g_vt + ((size_t)b * DM + n0) * SEQ + mloc;
        epi_store_T(c, Ct, SEQ);
    }
}

// ---------------------------------------------------------------------------
// Softmax (causal, single pass, row in registers). tf32-rounds P; zeroes to
// the 128-tile boundary so PV reads clean zeros.
// ---------------------------------------------------------------------------
__global__ __launch_bounds__(256) void softmax_kernel() {
    const int row = blockIdx.x;
    const int b = row >> 11;
    const int q = row & (SEQ - 1);
    float* __restrict__ S = g_s + (size_t)b * SEQ * SEQ + (size_t)q * SEQ;
    const int nvalid = q + 1;
    const int nzero = ((q >> 7) + 1) << 7;
    const int tid = threadIdx.x, wid = tid >> 5, lane = tid & 31;

    __shared__ float red[8];

    float v[8];
    float lmax = -CUDART_INF_F;
    #pragma unroll
    for (int j = 0; j < 8; ++j) {
        const int col = j * 256 + tid;
        if (col < nvalid) {
            v[j] = S[col] * SCALE;
            lmax = fmaxf(lmax, v[j]);
        }
    }
    #pragma unroll
    for (int o = 16; o > 0; o >>= 1)
        lmax = fmaxf(lmax, __shfl_xor_sync(0xFFFFFFFFu, lmax, o));
    if (lane == 0) red[wid] = lmax;
    __syncthreads();
    float rmax = red[0];
    #pragma unroll
    for (int w = 1; w < 8; ++w) rmax = fmaxf(rmax, red[w]);
    __syncthreads();

    float lsum = 0.0f;
    #pragma unroll
    for (int j = 0; j < 8; ++j) {
        const int col = j * 256 + tid;
        if (col < nvalid) {
            v[j] = __expf(v[j] - rmax);
            lsum += v[j];
        }
    }
    #pragma unroll
    for (int o = 16; o > 0; o >>= 1)
        lsum += __shfl_xor_sync(0xFFFFFFFFu, lsum, o);
    if (lane == 0) red[wid] = lsum;
    __syncthreads();
    float rsum = red[0];
    #pragma unroll
    for (int w = 1; w < 8; ++w) rsum += red[w];
    const float inv = 1.0f / rsum;

    #pragma unroll
    for (int j = 0; j < 8; ++j) {
        const int col = j * 256 + tid;
        if (col < nzero)
            S[col] = (col < nvalid) ? tf32r(v[j] * inv) : 0.0f;
    }
}

// ---------------------------------------------------------------------------
// GEMM 3: O = P @ V  (A = P, B = V^T, NT), K truncated at causal edge.
// ---------------------------------------------------------------------------
__global__ __launch_bounds__(256, 2) void pv_tc_kernel(float* __restrict__ out) {
    extern __shared__ float sm[];
    const int b = blockIdx.z;
    const long m0 = (long)blockIdx.y * BM;
    const long n0 = (long)blockIdx.x * BN;
    const float* A = g_s + ((size_t)b * SEQ + m0) * SEQ;
    const float* B = g_vt + ((size_t)b * DM + n0) * SEQ;
    const int nchunks = (int)((m0 + BM) / BK);

    float c[2][8][4];
    zero_c(c);
    gemm_tc(sm, A, SEQ, B, SEQ, nchunks, c);

    float* C = out + ((size_t)b * SEQ + m0) * DM + n0;
    epi_store(c, C, DM, false);
}

// ---------------------------------------------------------------------------
extern "C" void kernel_launch(void* const* d_in, const int* in_sizes, int n_in,
                              void* d_out, int out_size) {
    (void)in_sizes; (void)n_in; (void)out_size;
    const float* x  = (const float*)d_in[0];
    const float* Wq = (const float*)d_in[1];
    const float* Wk = (const float*)d_in[2];
    const float* Wv = (const float*)d_in[3];
    float* out = (float*)d_out;

    cudaFuncSetAttribute(qkv_qk_kernel, cudaFuncAttributeMaxDynamicSharedMemorySize, SMEM_BYTES);
    cudaFuncSetAttribute(scorev_kernel, cudaFuncAttributeMaxDynamicSharedMemorySize, SMEM_BYTES);
    cudaFuncSetAttribute(pv_tc_kernel,  cudaFuncAttributeMaxDynamicSharedMemorySize, SMEM_BYTES);

    roundx_kernel<<<(MROWS * DM / 4) / 256, 256>>>(x);
    {
        dim3 g(DM / 32, DM / 32, 3);
        dim3 blk(32, 8);
        wtrans_kernel<<<g, blk>>>(Wq, Wk, Wv);
    }
    {
        dim3 g(DM / BN, MROWS / BM, 2);              // 8 x 64 x 2 (Q, K)
        qkv_qk_kernel<<<g, 256, SMEM_BYTES>>>();
    }
    scorev_kernel<<<1056, 256, SMEM_BYTES>>>();      // 544 score + 512 V-proj
    softmax_kernel<<<BATCH * SEQ, 256>>>();
    {
        dim3 g(DM / BN, SEQ / BM, BATCH);            // 8 x 16 x 4
        pv_tc_kernel<<<g, 256, SMEM_BYTES>>>(out);
    }
}

// round 7
// speedup vs baseline: 3.7564x; 1.0123x over previous
#include <cuda_runtime.h>
#include <cstdint>
#include <math_constants.h>

#define BATCH 4
#define SEQ   2048
#define DM    1024
#define MROWS (BATCH * SEQ)
#define SCALE (1.0f / 32.0f)

// GEMM tiling
#define BM 128
#define BN 128
#define BK 32
#define LDS_T 40                     // 32 + 8 pad (floats): 8 mod 32 -> conflict-free
#define TILE_F (BM * LDS_T)          // 5120 floats per tile
#define STG_F  (2 * TILE_F)          // A+B per stage
#define SMEM_BYTES (2 * STG_F * 4)   // 81920 B (2 stages)

// Scratch (__device__ globals; allocation-free rule)
__device__ float g_xr[(size_t)MROWS * DM];          // x  (tf32-rounded)
__device__ float g_wt[(size_t)3 * DM * DM];         // W^T (tf32-rounded)
__device__ float g_q [(size_t)MROWS * DM];          // q  (tf32-rounded)
__device__ float g_k [(size_t)MROWS * DM];          // k  (tf32-rounded)
__device__ float g_vt[(size_t)MROWS * DM];          // V^T per batch [b][d][key], tf32
__device__ float g_s [(size_t)BATCH * SEQ * SEQ];   // scores / probs

// ---------------------------------------------------------------------------
__device__ __forceinline__ float tf32r(float x) {
    uint32_t u;
    asm("cvt.rna.tf32.f32 %0, %1;" : "=r"(u) : "f"(x));
    return __uint_as_float(u);
}

__device__ __forceinline__ void cp16(uint32_t dst, const void* src) {
    asm volatile("cp.async.cg.shared.global [%0], [%1], 16;"
                 :: "r"(dst), "l"(src) : "memory");
}

__device__ __forceinline__ void mma8(float* c, const uint32_t* a, const uint32_t* b) {
    asm volatile(
        "mma.sync.aligned.m16n8k8.row.col.f32.tf32.tf32.f32 "
        "{%0,%1,%2,%3}, {%4,%5,%6,%7}, {%8,%9}, {%0,%1,%2,%3};"
        : "+f"(c[0]), "+f"(c[1]), "+f"(c[2]), "+f"(c[3])
        : "r"(a[0]), "r"(a[1]), "r"(a[2]), "r"(a[3]), "r"(b[0]), "r"(b[1]));
}

// Issue cp.async for a 128x32-float K-major tile into padded SMEM.
__device__ __forceinline__ void load_tile(uint32_t smbase_b, const float* __restrict__ src,
                                          long ld, int tid) {
    #pragma unroll
    for (int i = 0; i < 4; ++i) {
        int idx = i * 256 + tid;
        int row = idx >> 3, c4 = idx & 7;
        cp16(smbase_b + (uint32_t)(row * LDS_T + c4 * 4) * 4,
             src + (size_t)row * ld + c4 * 4);
    }
}

// Load one ks-step of fragments via LDS.64 (k-permutation trick:
// logical k-slot lc <- physical col 8ks+2lc, slot lc+4 <- 8ks+2lc+1.
// mma's k-sum is permutation invariant as long as A and B agree).
__device__ __forceinline__ void load_frags(const float* __restrict__ a_sm,
                                           const float* __restrict__ b_sm,
                                           int ks, int warpM, int warpN,
                                           int lr, int lc,
                                           uint32_t* a, uint32_t* b) {
    const int k = ks * 8 + 2 * lc;
    #pragma unroll
    for (int t = 0; t < 2; ++t) {
        const int r = warpM * 32 + t * 16 + lr;
        const float2 v0 = *(const float2*)&a_sm[r * LDS_T + k];
        const float2 v1 = *(const float2*)&a_sm[(r + 8) * LDS_T + k];
        a[t * 4 + 0] = __float_as_uint(v0.x);   // logical (lr,   lc)
        a[t * 4 + 1] = __float_as_uint(v1.x);   // logical (lr+8, lc)
        a[t * 4 + 2] = __float_as_uint(v0.y);   // logical (lr,   lc+4)
        a[t * 4 + 3] = __float_as_uint(v1.y);   // logical (lr+8, lc+4)
    }
    #pragma unroll
    for (int u = 0; u < 8; ++u) {
        const int n = warpN * 64 + u * 8 + lr;
        const float2 w = *(const float2*)&b_sm[n * LDS_T + k];
        b[u * 2 + 0] = __float_as_uint(w.x);    // logical (lc,   n)
        b[u * 2 + 1] = __float_as_uint(w.y);    // logical (lc+4, n)
    }
}

// ---------------------------------------------------------------------------
// NT GEMM mainloop: C(128x128) += A(128xK) * B(128xK)^T, both K-major.
// 2-stage cp.async pipeline, 1 barrier/chunk, ks-level register pipelining.
// ---------------------------------------------------------------------------
__device__ __forceinline__ void gemm_tc(float* sm,
                                        const float* __restrict__ A, long lda,
                                        const float* __restrict__ B, long ldb,
                                        int nchunks, float c[2][8][4]) {
    const int tid = threadIdx.x, wid = tid >> 5, lane = tid & 31;
    const int warpM = wid & 3, warpN = wid >> 2;
    const int lr = lane >> 2, lc = lane & 3;
    const uint32_t smu = (uint32_t)__cvta_generic_to_shared(sm);

    load_tile(smu, A, lda, tid);
    load_tile(smu + TILE_F * 4, B, ldb, tid);
    asm volatile("cp.async.commit_group;" ::: "memory");

    for (int i = 0; i < nchunks; ++i) {
        asm volatile("cp.async.wait_group 0;" ::: "memory");
        __syncthreads();

        if (i + 1 < nchunks) {
            const uint32_t s = (uint32_t)((i + 1) & 1) * STG_F * 4;
            load_tile(smu + s, A + (size_t)(i + 1) * BK, lda, tid);
            load_tile(smu + s + TILE_F * 4, B + (size_t)(i + 1) * BK, ldb, tid);
            asm volatile("cp.async.commit_group;" ::: "memory");
        }

        const float* a_sm = sm + (i & 1) * STG_F;
        const float* b_sm = a_sm + TILE_F;

        uint32_t aA[8], bA[16], aB[8], bB[16];
        load_frags(a_sm, b_sm, 0, warpM, warpN, lr, lc, aA, bA);
        #pragma unroll
        for (int ks = 0; ks < 4; ++ks) {
            if (ks < 3)
                load_frags(a_sm, b_sm, ks + 1, warpM, warpN, lr, lc,
                           (ks & 1) ? aA : aB, (ks & 1) ? bA : bB);
            const uint32_t* a = (ks & 1) ? aB : aA;
            const uint32_t* b = (ks & 1) ? bB : bA;
            #pragma unroll
            for (int t = 0; t < 2; ++t)
                #pragma unroll
                for (int u = 0; u < 8; ++u)
                    mma8(c[t][u], a + t * 4, b + u * 2);
        }
    }
}

__device__ __forceinline__ void zero_c(float c[2][8][4]) {
    #pragma unroll
    for (int t = 0; t < 2; ++t)
        #pragma unroll
        for (int u = 0; u < 8; ++u)
            #pragma unroll
            for (int j = 0; j < 4; ++j) c[t][u][j] = 0.0f;
}

// Row-major epilogue (optional tf32 rounding).
__device__ __forceinline__ void epi_store(float c[2][8][4], float* __restrict__ C,
                                          long ldc, bool rnd) {
    const int tid = threadIdx.x, wid = tid >> 5, lane = tid & 31;
    const int warpM = wid & 3, warpN = wid >> 2;
    const int lr = lane >> 2, lc = lane & 3;
    #pragma unroll
    for (int t = 0; t < 2; ++t)
        #pragma unroll
        for (int u = 0; u < 8; ++u) {
            const int r = warpM * 32 + t * 16 + lr;
            const int n = warpN * 64 + u * 8 + lc * 2;
            float2 v0 = make_float2(c[t][u][0], c[t][u][1]);
            float2 v1 = make_float2(c[t][u][2], c[t][u][3]);
            if (rnd) {
                v0.x = tf32r(v0.x); v0.y = tf32r(v0.y);
                v1.x = tf32r(v1.x); v1.y = tf32r(v1.y);
            }
            *(float2*)&C[(size_t)r * ldc + n]       = v0;
            *(float2*)&C[(size_t)(r + 8) * ldc + n] = v1;
        }
}

// Transposed epilogue: Ct[n][m], tf32-rounded (for V^T).
__device__ __forceinline__ void epi_store_T(float c[2][8][4], float* __restrict__ Ct,
                                            long ldm) {
    const int tid = threadIdx.x, wid = tid >> 5, lane = tid & 31;
    const int warpM = wid & 3, warpN = wid >> 2;
    const int lr = lane >> 2, lc = lane & 3;
    #pragma unroll
    for (int t = 0; t < 2; ++t)
        #pragma unroll
        for (int u = 0; u < 8; ++u) {
            const int r = warpM * 32 + t * 16 + lr;
            const int n = warpN * 64 + u * 8 + lc * 2;
            Ct[(size_t)n * ldm + r]           = tf32r(c[t][u][0]);
            Ct[(size_t)(n + 1) * ldm + r]     = tf32r(c[t][u][1]);
            Ct[(size_t)n * ldm + r + 8]       = tf32r(c[t][u][2]);
            Ct[(size_t)(n + 1) * ldm + r + 8] = tf32r(c[t][u][3]);
        }
}

// ---------------------------------------------------------------------------
// Pre-pass kernels
// ---------------------------------------------------------------------------
__global__ __launch_bounds__(256) void roundx_kernel(const float* __restrict__ x) {
    size_t i = (size_t)blockIdx.x * blockDim.x + threadIdx.x;
    float4 v = ((const float4*)x)[i];
    v.x = tf32r(v.x); v.y = tf32r(v.y); v.z = tf32r(v.z); v.w = tf32r(v.w);
    ((float4*)g_xr)[i] = v;
}

__global__ __launch_bounds__(256) void wtrans_kernel(const float* __restrict__ Wq,
                                                     const float* __restrict__ Wk,
                                                     const float* __restrict__ Wv) {
    __shared__ float t[32][33];
    const int z = blockIdx.z;
    const float* __restrict__ W = (z == 0) ? Wq : (z == 1 ? Wk : Wv);
    float* __restrict__ O = g_wt + (size_t)z * DM * DM;
    const int tx = threadIdx.x, ty = threadIdx.y;
    const int n = blockIdx.x * 32 + tx;
    const int k0 = blockIdx.y * 32;
    for (int i = ty; i < 32; i += 8) t[i][tx] = W[(size_t)(k0 + i) * DM + n];
    __syncthreads();
    const int ko = blockIdx.y * 32 + tx;
    const int n0 = blockIdx.x * 32;
    for (int i = ty; i < 32; i += 8)
        O[(size_t)(n0 + i) * DM + ko] = tf32r(t[tx][i]);
}

// ---------------------------------------------------------------------------
// GEMM 1: Q and K projections only (z: 0=q, 1=k).
// ---------------------------------------------------------------------------
__global__ __launch_bounds__(256, 2) void qkv_qk_kernel() {
    extern __shared__ float sm[];
    const int z = blockIdx.z;
    const long m0 = (long)blockIdx.y * BM;
    const long n0 = (long)blockIdx.x * BN;
    const float* A = g_xr + (size_t)m0 * DM;
    const float* B = g_wt + (size_t)z * DM * DM + (size_t)n0 * DM;

    float c[2][8][4];
    zero_c(c);
    gemm_tc(sm, A, DM, B, DM, DM / BK, c);

    float* C = (z == 0 ? g_q : g_k) + (size_t)m0 * DM + n0;
    epi_store(c, C, DM, true);
}

// ---------------------------------------------------------------------------
// GEMM 2 (merged): ids [0,544): S = Q@K^T lower-tri tiles.
//                  ids [544,1056): V-projection -> V^T (independent work).
// ---------------------------------------------------------------------------
__global__ __launch_bounds__(256, 2) void scorev_kernel() {
    extern __shared__ float sm[];
    const int id = blockIdx.x;
    float c[2][8][4];
    zero_c(c);

    if (id < 544) {
        const int b = id / 136;
        const int tt = id - b * 136;
        int by = (int)((sqrtf(8.0f * tt + 1.0f) - 1.0f) * 0.5f);
        while ((by + 1) * (by + 2) / 2 <= tt) ++by;
        while (by * (by + 1) / 2 > tt) --by;
        const int bx = tt - by * (by + 1) / 2;

        const long m0 = (long)by * BM;
        const long n0 = (long)bx * BN;
        const float* A = g_q + ((size_t)b * SEQ + m0) * DM;
        const float* B = g_k + ((size_t)b * SEQ + n0) * DM;

        gemm_tc(sm, A, DM, B, DM, DM / BK, c);

        float* C = g_s + ((size_t)b * SEQ + m0) * SEQ + n0;
        epi_store(c, C, SEQ, false);
    } else {
        const int r = id - 544;
        const long n0 = (long)(r & 7) * BN;
        const long m0 = (long)(r >> 3) * BM;
        const float* A = g_xr + (size_t)m0 * DM;
        const float* B = g_wt + (size_t)2 * DM * DM + (size_t)n0 * DM;

        gemm_tc(sm, A, DM, B, DM, DM / BK, c);

        const int b = (int)(m0 / SEQ);
        const long mloc = m0 - (long)b * SEQ;
        float* Ct = g_vt + ((size_t)b * DM + n0) * SEQ + mloc;
        epi_store_T(c, Ct, SEQ);
    }
}

// ---------------------------------------------------------------------------
// Softmax (causal, single pass, row in registers). tf32-rounds P; zeroes to
// the 128-tile boundary so PV reads clean zeros.
// ---------------------------------------------------------------------------
__global__ __launch_bounds__(256) void softmax_kernel() {
    const int row = blockIdx.x;
    const int b = row >> 11;
    const int q = row & (SEQ - 1);
    float* __restrict__ S = g_s + (size_t)b * SEQ * SEQ + (size_t)q * SEQ;
    const int nvalid = q + 1;
    const int nzero = ((q >> 7) + 1) << 7;
    const int tid = threadIdx.x, wid = tid >> 5, lane = tid & 31;

    __shared__ float red[8];

    float v[8];
    float lmax = -CUDART_INF_F;
    #pragma unroll
    for (int j = 0; j < 8; ++j) {
        const int col = j * 256 + tid;
        if (col < nvalid) {
            v[j] = S[col] * SCALE;
            lmax = fmaxf(lmax, v[j]);
        }
    }
    #pragma unroll
    for (int o = 16; o > 0; o >>= 1)
        lmax = fmaxf(lmax, __shfl_xor_sync(0xFFFFFFFFu, lmax, o));
    if (lane == 0) red[wid] = lmax;
    __syncthreads();
    float rmax = red[0];
    #pragma unroll
    for (int w = 1; w < 8; ++w) rmax = fmaxf(rmax, red[w]);
    __syncthreads();

    float lsum = 0.0f;
    #pragma unroll
    for (int j = 0; j < 8; ++j) {
        const int col = j * 256 + tid;
        if (col < nvalid) {
            v[j] = __expf(v[j] - rmax);
            lsum += v[j];
        }
    }
    #pragma unroll
    for (int o = 16; o > 0; o >>= 1)
        lsum += __shfl_xor_sync(0xFFFFFFFFu, lsum, o);
    if (lane == 0) red[wid] = lsum;
    __syncthreads();
    float rsum = red[0];
    #pragma unroll
    for (int w = 1; w < 8; ++w) rsum += red[w];
    const float inv = 1.0f / rsum;

    #pragma unroll
    for (int j = 0; j < 8; ++j) {
        const int col = j * 256 + tid;
        if (col < nzero)
            S[col] = (col < nvalid) ? tf32r(v[j] * inv) : 0.0f;
    }
}

// ---------------------------------------------------------------------------
// GEMM 3: O = P @ V  (A = P, B = V^T, NT), K truncated at causal edge.
// ---------------------------------------------------------------------------
__global__ __launch_bounds__(256, 2) void pv_tc_kernel(float* __restrict__ out) {
    extern __shared__ float sm[];
    const int b = blockIdx.z;
    const long m0 = (long)blockIdx.y * BM;
    const long n0 = (long)blockIdx.x * BN;
    const float* A = g_s + ((size_t)b * SEQ + m0) * SEQ;
    const float* B = g_vt + ((size_t)b * DM + n0) * SEQ;
    const int nchunks = (int)((m0 + BM) / BK);

    float c[2][8][4];
    zero_c(c);
    gemm_tc(sm, A, SEQ, B, SEQ, nchunks, c);

    float* C = out + ((size_t)b * SEQ + m0) * DM + n0;
    epi_store(c, C, DM, false);
}

// ---------------------------------------------------------------------------
extern "C" void kernel_launch(void* const* d_in, const int* in_sizes, int n_in,
                              void* d_out, int out_size) {
    (void)in_sizes; (void)n_in; (void)out_size;
    const float* x  = (const float*)d_in[0];
    const float* Wq = (const float*)d_in[1];
    const float* Wk = (const float*)d_in[2];
    const float* Wv = (const float*)d_in[3];
    float* out = (float*)d_out;

    cudaFuncSetAttribute(qkv_qk_kernel, cudaFuncAttributeMaxDynamicSharedMemorySize, SMEM_BYTES);
    cudaFuncSetAttribute(scorev_kernel, cudaFuncAttributeMaxDynamicSharedMemorySize, SMEM_BYTES);
    cudaFuncSetAttribute(pv_tc_kernel,  cudaFuncAttributeMaxDynamicSharedMemorySize, SMEM_BYTES);

    roundx_kernel<<<(MROWS * DM / 4) / 256, 256>>>(x);
    {
        dim3 g(DM / 32, DM / 32, 3);
        dim3 blk(32, 8);
        wtrans_kernel<<<g, blk>>>(Wq, Wk, Wv);
    }
    {
        dim3 g(DM / BN, MROWS / BM, 2);              // 8 x 64 x 2 (Q, K)
        qkv_qk_kernel<<<g, 256, SMEM_BYTES>>>();
    }
    scorev_kernel<<<1056, 256, SMEM_BYTES>>>();      // 544 score + 512 V-proj
    softmax_kernel<<<BATCH * SEQ, 256>>>();
    {
        dim3 g(DM / BN, SEQ / BM, BATCH);            // 8 x 16 x 4
        pv_tc_kernel<<<g, 256, SMEM_BYTES>>>(out);
    }
}

// round 8
// speedup vs baseline: 4.2840x; 1.1404x over previous
#include <cuda_runtime.h>
#include <cstdint>
#include <math_constants.h>

#define BATCH 4
#define SEQ   2048
#define DM    1024
#define MROWS (BATCH * SEQ)
#define SCALE (1.0f / 32.0f)

// GEMM tiling
#define BM 128
#define BN 128
#define BK 32
#define LDS_T 40                     // 32 + 8 pad (floats): 8 mod 32 -> conflict-free
#define TILE_F (BM * LDS_T)          // 5120 floats per tile
#define STG_F  (2 * TILE_F)          // A+B per stage
#define SMEM_BYTES (2 * STG_F * 4)   // 81920 B (2 stages)

// Scratch (__device__ globals; allocation-free rule)
__device__ float g_xr[(size_t)MROWS * DM];          // x  (tf32-rounded)
__device__ float g_wt[(size_t)3 * DM * DM];         // W^T (tf32-rounded)
__device__ float g_q [(size_t)MROWS * DM];          // q  (tf32-rounded)
__device__ float g_k [(size_t)MROWS * DM];          // k  (tf32-rounded)
__device__ float g_vt[(size_t)MROWS * DM];          // V^T per batch [b][d][key], tf32
__device__ float g_s [(size_t)BATCH * SEQ * SEQ];   // scores / probs

// ---------------------------------------------------------------------------
__device__ __forceinline__ float tf32r(float x) {
    uint32_t u;
    asm("cvt.rna.tf32.f32 %0, %1;" : "=r"(u) : "f"(x));
    return __uint_as_float(u);
}

__device__ __forceinline__ void cp16(uint32_t dst, const void* src) {
    asm volatile("cp.async.cg.shared.global [%0], [%1], 16;"
                 :: "r"(dst), "l"(src) : "memory");
}

__device__ __forceinline__ void mma8(float* c, const uint32_t* a, const uint32_t* b) {
    asm volatile(
        "mma.sync.aligned.m16n8k8.row.col.f32.tf32.tf32.f32 "
        "{%0,%1,%2,%3}, {%4,%5,%6,%7}, {%8,%9}, {%0,%1,%2,%3};"
        : "+f"(c[0]), "+f"(c[1]), "+f"(c[2]), "+f"(c[3])
        : "r"(a[0]), "r"(a[1]), "r"(a[2]), "r"(a[3]), "r"(b[0]), "r"(b[1]));
}

// Issue cp.async for a 128x32-float K-major tile into padded SMEM.
__device__ __forceinline__ void load_tile(uint32_t smbase_b, const float* __restrict__ src,
                                          long ld, int tid) {
    #pragma unroll
    for (int i = 0; i < 4; ++i) {
        int idx = i * 256 + tid;
        int row = idx >> 3, c4 = idx & 7;
        cp16(smbase_b + (uint32_t)(row * LDS_T + c4 * 4) * 4,
             src + (size_t)row * ld + c4 * 4);
    }
}

// Load one ks-step of fragments via LDS.64 from precomputed per-thread base
// pointers; all offsets are compile-time immediates.
// k-permutation trick: logical k-slot lc <- physical col 8ks+2lc, slot lc+4
// <- 8ks+2lc+1 (mma's k-sum is permutation invariant as long as A,B agree).
__device__ __forceinline__ void load_frags(const float* __restrict__ aP,
                                           const float* __restrict__ bP,
                                           int ks, uint32_t* a, uint32_t* b) {
    const int k = ks * 8;
    const float2 v0 = *(const float2*)(aP + k);                  // t=0, row+0
    const float2 v1 = *(const float2*)(aP + 8 * LDS_T + k);      // t=0, row+8
    const float2 v2 = *(const float2*)(aP + 16 * LDS_T + k);     // t=1, row+0
    const float2 v3 = *(const float2*)(aP + 24 * LDS_T + k);     // t=1, row+8
    a[0] = __float_as_uint(v0.x); a[1] = __float_as_uint(v1.x);
    a[2] = __float_as_uint(v0.y); a[3] = __float_as_uint(v1.y);
    a[4] = __float_as_uint(v2.x); a[5] = __float_as_uint(v3.x);
    a[6] = __float_as_uint(v2.y); a[7] = __float_as_uint(v3.y);
    #pragma unroll
    for (int u = 0; u < 8; ++u) {
        const float2 w = *(const float2*)(bP + u * 8 * LDS_T + k);
        b[u * 2 + 0] = __float_as_uint(w.x);
        b[u * 2 + 1] = __float_as_uint(w.y);
    }
}

// ---------------------------------------------------------------------------
// NT GEMM mainloop: C(128x128) += A(128xK) * B(128xK)^T, both K-major.
// 2-stage cp.async pipeline, 1 barrier/chunk, ks-level register pipelining,
// immediate-offset fragment addressing.
// ---------------------------------------------------------------------------
__device__ __forceinline__ void gemm_tc(float* sm,
                                        const float* __restrict__ A, long lda,
                                        const float* __restrict__ B, long ldb,
                                        int nchunks, float c[2][8][4]) {
    const int tid = threadIdx.x, wid = tid >> 5, lane = tid & 31;
    const int warpM = wid & 3, warpN = wid >> 2;
    const int lr = lane >> 2, lc = lane & 3;
    const uint32_t smu = (uint32_t)__cvta_generic_to_shared(sm);

    // Per-thread fragment base pointers (stage 0 / stage 1).
    const float* aP0 = sm + (warpM * 32 + lr) * LDS_T + 2 * lc;
    const float* bP0 = sm + TILE_F + (warpN * 64 + lr) * LDS_T + 2 * lc;
    const float* aP1 = aP0 + STG_F;
    const float* bP1 = bP0 + STG_F;

    load_tile(smu, A, lda, tid);
    load_tile(smu + TILE_F * 4, B, ldb, tid);
    asm volatile("cp.async.commit_group;" ::: "memory");

    for (int i = 0; i < nchunks; ++i) {
        asm volatile("cp.async.wait_group 0;" ::: "memory");
        __syncthreads();

        const float* aP = (i & 1) ? aP1 : aP0;
        const float* bP = (i & 1) ? bP1 : bP0;

        // Critical path first: ks=0 fragments.
        uint32_t aA[8], bA[16], aB[8], bB[16];
        load_frags(aP, bP, 0, aA, bA);

        // Prefetch chunk i+1 into the other stage (overlaps with MMA below).
        if (i + 1 < nchunks) {
            const uint32_t s = (uint32_t)((i + 1) & 1) * STG_F * 4;
            load_tile(smu + s, A + (size_t)(i + 1) * BK, lda, tid);
            load_tile(smu + s + TILE_F * 4, B + (size_t)(i + 1) * BK, ldb, tid);
            asm volatile("cp.async.commit_group;" ::: "memory");
        }

        #pragma unroll
        for (int ks = 0; ks < 4; ++ks) {
            if (ks < 3)
                load_frags(aP, bP, ks + 1,
                           (ks & 1) ? aA : aB, (ks & 1) ? bA : bB);
            const uint32_t* a = (ks & 1) ? aB : aA;
            const uint32_t* b = (ks & 1) ? bB : bA;
            #pragma unroll
            for (int t = 0; t < 2; ++t)
                #pragma unroll
                for (int u = 0; u < 8; ++u)
                    mma8(c[t][u], a + t * 4, b + u * 2);
        }
    }
}

__device__ __forceinline__ void zero_c(float c[2][8][4]) {
    #pragma unroll
    for (int t = 0; t < 2; ++t)
        #pragma unroll
        for (int u = 0; u < 8; ++u)
            #pragma unroll
            for (int j = 0; j < 4; ++j) c[t][u][j] = 0.0f;
}

// Row-major epilogue (optional tf32 rounding).
__device__ __forceinline__ void epi_store(float c[2][8][4], float* __restrict__ C,
                                          long ldc, bool rnd) {
    const int tid = threadIdx.x, wid = tid >> 5, lane = tid & 31;
    const int warpM = wid & 3, warpN = wid >> 2;
    const int lr = lane >> 2, lc = lane & 3;
    #pragma unroll
    for (int t = 0; t < 2; ++t)
        #pragma unroll
        for (int u = 0; u < 8; ++u) {
            const int r = warpM * 32 + t * 16 + lr;
            const int n = warpN * 64 + u * 8 + lc * 2;
            float2 v0 = make_float2(c[t][u][0], c[t][u][1]);
            float2 v1 = make_float2(c[t][u][2], c[t][u][3]);
            if (rnd) {
                v0.x = tf32r(v0.x); v0.y = tf32r(v0.y);
                v1.x = tf32r(v1.x); v1.y = tf32r(v1.y);
            }
            *(float2*)&C[(size_t)r * ldc + n]       = v0;
            *(float2*)&C[(size_t)(r + 8) * ldc + n] = v1;
        }
}

// Transposed epilogue: Ct[n][m], tf32-rounded (for V^T).
__device__ __forceinline__ void epi_store_T(float c[2][8][4], float* __restrict__ Ct,
                                            long ldm) {
    const int tid = threadIdx.x, wid = tid >> 5, lane = tid & 31;
    const int warpM = wid & 3, warpN = wid >> 2;
    const int lr = lane >> 2, lc = lane & 3;
    #pragma unroll
    for (int t = 0; t < 2; ++t)
        #pragma unroll
        for (int u = 0; u < 8; ++u) {
            const int r = warpM * 32 + t * 16 + lr;
            const int n = warpN * 64 + u * 8 + lc * 2;
            Ct[(size_t)n * ldm + r]           = tf32r(c[t][u][0]);
            Ct[(size_t)(n + 1) * ldm + r]     = tf32r(c[t][u][1]);
            Ct[(size_t)n * ldm + r + 8]       = tf32r(c[t][u][2]);
            Ct[(size_t)(n + 1) * ldm + r + 8] = tf32r(c[t][u][3]);
        }
}

// ---------------------------------------------------------------------------
// Pre-pass kernels
// ---------------------------------------------------------------------------
__global__ __launch_bounds__(256) void roundx_kernel(const float* __restrict__ x) {
    size_t i = (size_t)blockIdx.x * blockDim.x + threadIdx.x;
    float4 v = ((const float4*)x)[i];
    v.x = tf32r(v.x); v.y = tf32r(v.y); v.z = tf32r(v.z); v.w = tf32r(v.w);
    ((float4*)g_xr)[i] = v;
}

__global__ __launch_bounds__(256) void wtrans_kernel(const float* __restrict__ Wq,
                                                     const float* __restrict__ Wk,
                                                     const float* __restrict__ Wv) {
    __shared__ float t[32][33];
    const int z = blockIdx.z;
    const float* __restrict__ W = (z == 0) ? Wq : (z == 1 ? Wk : Wv);
    float* __restrict__ O = g_wt + (size_t)z * DM * DM;
    const int tx = threadIdx.x, ty = threadIdx.y;
    const int n = blockIdx.x * 32 + tx;
    const int k0 = blockIdx.y * 32;
    for (int i = ty; i < 32; i += 8) t[i][tx] = W[(size_t)(k0 + i) * DM + n];
    __syncthreads();
    const int ko = blockIdx.y * 32 + tx;
    const int n0 = blockIdx.x * 32;
    for (int i = ty; i < 32; i += 8)
        O[(size_t)(n0 + i) * DM + ko] = tf32r(t[tx][i]);
}

// ---------------------------------------------------------------------------
// GEMM 1: Q and K projections only (z: 0=q, 1=k).
// ---------------------------------------------------------------------------
__global__ __launch_bounds__(256, 2) void qkv_qk_kernel() {
    extern __shared__ float sm[];
    const int z = blockIdx.z;
    const long m0 = (long)blockIdx.y * BM;
    const long n0 = (long)blockIdx.x * BN;
    const float* A = g_xr + (size_t)m0 * DM;
    const float* B = g_wt + (size_t)z * DM * DM + (size_t)n0 * DM;

    float c[2][8][4];
    zero_c(c);
    gemm_tc(sm, A, DM, B, DM, DM / BK, c);

    float* C = (z == 0 ? g_q : g_k) + (size_t)m0 * DM + n0;
    epi_store(c, C, DM, true);
}

// ---------------------------------------------------------------------------
// GEMM 2 (merged): ids [0,544): S = Q@K^T lower-tri tiles.
//                  ids [544,1056): V-projection -> V^T (independent work).
// ---------------------------------------------------------------------------
__global__ __launch_bounds__(256, 2) void scorev_kernel() {
    extern __shared__ float sm[];
    const int id = blockIdx.x;
    float c[2][8][4];
    zero_c(c);

    if (id < 544) {
        const int b = id / 136;
        const int tt = id - b * 136;
        int by = (int)((sqrtf(8.0f * tt + 1.0f) - 1.0f) * 0.5f);
        while ((by + 1) * (by + 2) / 2 <= tt) ++by;
        while (by * (by + 1) / 2 > tt) --by;
        const int bx = tt - by * (by + 1) / 2;

        const long m0 = (long)by * BM;
        const long n0 = (long)bx * BN;
        const float* A = g_q + ((size_t)b * SEQ + m0) * DM;
        const float* B = g_k + ((size_t)b * SEQ + n0) * DM;

        gemm_tc(sm, A, DM, B, DM, DM / BK, c);

        float* C = g_s + ((size_t)b * SEQ + m0) * SEQ + n0;
        epi_store(c, C, SEQ, false);
    } else {
        const int r = id - 544;
        const long n0 = (long)(r & 7) * BN;
        const long m0 = (long)(r >> 3) * BM;
        const float* A = g_xr + (size_t)m0 * DM;
        const float* B = g_wt + (size_t)2 * DM * DM + (size_t)n0 * DM;

        gemm_tc(sm, A, DM, B, DM, DM / BK, c);

        const int b = (int)(m0 / SEQ);
        const long mloc = m0 - (long)b * SEQ;
        float* Ct = g_vt + ((size_t)b * DM + n0) * SEQ + mloc;
        epi_store_T(c, Ct, SEQ);
    }
}

// ---------------------------------------------------------------------------
// Softmax (causal, single pass, row in registers). tf32-rounds P; zeroes to
// the 128-tile boundary so PV reads clean zeros.
// ---------------------------------------------------------------------------
__global__ __launch_bounds__(256) void softmax_kernel() {
    const int row = blockIdx.x;
    const int b = row >> 11;
    const int q = row & (SEQ - 1);
    float* __restrict__ S = g_s + (size_t)b * SEQ * SEQ + (size_t)q * SEQ;
    const int nvalid = q + 1;
    const int nzero = ((q >> 7) + 1) << 7;
    const int tid = threadIdx.x, wid = tid >> 5, lane = tid & 31;

    __shared__ float red[8];

    float v[8];
    float lmax = -CUDART_INF_F;
    #pragma unroll
    for (int j = 0; j < 8; ++j) {
        const int col = j * 256 + tid;
        if (col < nvalid) {
            v[j] = S[col] * SCALE;
            lmax = fmaxf(lmax, v[j]);
        }
    }
    #pragma unroll
    for (int o = 16; o > 0; o >>= 1)
        lmax = fmaxf(lmax, __shfl_xor_sync(0xFFFFFFFFu, lmax, o));
    if (lane == 0) red[wid] = lmax;
    __syncthreads();
    float rmax = red[0];
    #pragma unroll
    for (int w = 1; w < 8; ++w) rmax = fmaxf(rmax, red[w]);
    __syncthreads();

    float lsum = 0.0f;
    #pragma unroll
    for (int j = 0; j < 8; ++j) {
        const int col = j * 256 + tid;
        if (col < nvalid) {
            v[j] = __expf(v[j] - rmax);
            lsum += v[j];
        }
    }
    #pragma unroll
    for (int o = 16; o > 0; o >>= 1)
        lsum += __shfl_xor_sync(0xFFFFFFFFu, lsum, o);
    if (lane == 0) red[wid] = lsum;
    __syncthreads();
    float rsum = red[0];
    #pragma unroll
    for (int w = 1; w < 8; ++w) rsum += red[w];
    const float inv = 1.0f / rsum;

    #pragma unroll
    for (int j = 0; j < 8; ++j) {
        const int col = j * 256 + tid;
        if (col < nzero)
            S[col] = (col < nvalid) ? tf32r(v[j] * inv) : 0.0f;
    }
}

// ---------------------------------------------------------------------------
// GEMM 3: O = P @ V  (A = P, B = V^T, NT), K truncated at causal edge.
// Heavy tiles (large m0) scheduled first for better wave balance.
// ---------------------------------------------------------------------------
__global__ __launch_bounds__(256, 2) void pv_tc_kernel(float* __restrict__ out) {
    extern __shared__ float sm[];
    const int b = blockIdx.z;
    const long m0 = (long)(gridDim.y - 1 - blockIdx.y) * BM;   // heavy-first
    const long n0 = (long)blockIdx.x * BN;
    const float* A = g_s + ((size_t)b * SEQ + m0) * SEQ;
    const float* B = g_vt + ((size_t)b * DM + n0) * SEQ;
    const int nchunks = (int)((m0 + BM) / BK);

    float c[2][8][4];
    zero_c(c);
    gemm_tc(sm, A, SEQ, B, SEQ, nchunks, c);

    float* C = out + ((size_t)b * SEQ + m0) * DM + n0;
    epi_store(c, C, DM, false);
}

// ---------------------------------------------------------------------------
extern "C" void kernel_launch(void* const* d_in, const int* in_sizes, int n_in,
                              void* d_out, int out_size) {
    (void)in_sizes; (void)n_in; (void)out_size;
    const float* x  = (const float*)d_in[0];
    const float* Wq = (const float*)d_in[1];
    const float* Wk = (const float*)d_in[2];
    const float* Wv = (const float*)d_in[3];
    float* out = (float*)d_out;

    cudaFuncSetAttribute(qkv_qk_kernel, cudaFuncAttributeMaxDynamicSharedMemorySize, SMEM_BYTES);
    cudaFuncSetAttribute(scorev_kernel, cudaFuncAttributeMaxDynamicSharedMemorySize, SMEM_BYTES);
    cudaFuncSetAttribute(pv_tc_kernel,  cudaFuncAttributeMaxDynamicSharedMemorySize, SMEM_BYTES);

    roundx_kernel<<<(MROWS * DM / 4) / 256, 256>>>(x);
    {
        dim3 g(DM / 32, DM / 32, 3);
        dim3 blk(32, 8);
        wtrans_kernel<<<g, blk>>>(Wq, Wk, Wv);
    }
    {
        dim3 g(DM / BN, MROWS / BM, 2);              // 8 x 64 x 2 (Q, K)
        qkv_qk_kernel<<<g, 256, SMEM_BYTES>>>();
    }
    scorev_kernel<<<1056, 256, SMEM_BYTES>>>();      // 544 score + 512 V-proj
    softmax_kernel<<<BATCH * SEQ, 256>>>();
    {
        dim3 g(DM / BN, SEQ / BM, BATCH);            // 8 x 16 x 4
        pv_tc_kernel<<<g, 256, SMEM_BYTES>>>(out);
    }
}

// round 10
// speedup vs baseline: 7.5578x; 1.7642x over previous
#include <cuda_runtime.h>
#include <cuda_fp16.h>
#include <cstdint>
#include <math_constants.h>

#define BATCH 4
#define SEQ   2048
#define DM    1024
#define MROWS (BATCH * SEQ)
#define SCALE (1.0f / 32.0f)

// GEMM tiling (fp16 operands, fp32 accum)
#define BM 128
#define BN 128
#define BK 64
#define S_H 80                        // row stride in fp16 (64 + 16 pad)
#define TILE_H (BM * S_H)             // 10240 halfs per tile (20480 B)
#define STG_H  (2 * TILE_H)           // A+B per stage
#define SMEM_BYTES (2 * STG_H * 2)    // 81920 B (2 stages)

// Scratch (__device__ globals; allocation-free rule)
__device__ __half g_xh [(size_t)MROWS * DM];         // x   (fp16)
__device__ __half g_wth[(size_t)3 * DM * DM];        // W^T (fp16)
__device__ __half g_qh [(size_t)MROWS * DM];         // Q   (fp16)
__device__ __half g_kh [(size_t)MROWS * DM];         // K   (fp16)
__device__ __half g_vth[(size_t)MROWS * DM];         // V^T per batch [b][d][key]
__device__ float  g_s  [(size_t)BATCH * SEQ * SEQ];  // scores (fp32)
__device__ __half g_ph [(size_t)BATCH * SEQ * SEQ];  // probs  (fp16)

// ---------------------------------------------------------------------------
__device__ __forceinline__ void cp16(uint32_t dst, const void* src) {
    asm volatile("cp.async.cg.shared.global [%0], [%1], 16;"
                 :: "r"(dst), "l"(src) : "memory");
}

__device__ __forceinline__ void mma16(float* c, const uint32_t* a, const uint32_t* b) {
    asm volatile(
        "mma.sync.aligned.m16n8k16.row.col.f32.f16.f16.f32 "
        "{%0,%1,%2,%3}, {%4,%5,%6,%7}, {%8,%9}, {%0,%1,%2,%3};"
        : "+f"(c[0]), "+f"(c[1]), "+f"(c[2]), "+f"(c[3])
        : "r"(a[0]), "r"(a[1]), "r"(a[2]), "r"(a[3]), "r"(b[0]), "r"(b[1]));
}

// Issue cp.async for a 128x64-fp16 K-major tile into padded SMEM.
__device__ __forceinline__ void load_tile(uint32_t smbase_b, const __half* __restrict__ src,
                                          long ld, int tid) {
    #pragma unroll
    for (int i = 0; i < 4; ++i) {
        int idx = i * 256 + tid;
        int row = idx >> 3, c8 = idx & 7;
        cp16(smbase_b + (uint32_t)(row * (S_H * 2) + c8 * 16),
             src + (size_t)row * ld + c8 * 8);
    }
}

// Load one k16-step of fragments via LDS.64, immediate offsets.
// k-permutation: quad-lane lc reads physical cols 4lc..4lc+3 as logical
// {2lc, 2lc+1, 2lc+8, 2lc+9}; A and B agree, so the k-sum is unchanged.
__device__ __forceinline__ void load_frags(const __half* __restrict__ aP,
                                           const __half* __restrict__ bP,
                                           int ks, uint32_t* a, uint32_t* b) {
    const int k = ks * 16;
    const uint2 u0 = *(const uint2*)(aP + k);               // t=0 row lr
    const uint2 u1 = *(const uint2*)(aP + 8 * S_H + k);     // t=0 row lr+8
    const uint2 u2 = *(const uint2*)(aP + 16 * S_H + k);    // t=1 row lr
    const uint2 u3 = *(const uint2*)(aP + 24 * S_H + k);    // t=1 row lr+8
    a[0] = u0.x; a[1] = u1.x; a[2] = u0.y; a[3] = u1.y;
    a[4] = u2.x; a[5] = u3.x; a[6] = u2.y; a[7] = u3.y;
    #pragma unroll
    for (int u = 0; u < 8; ++u) {
        const uint2 w = *(const uint2*)(bP + u * 8 * S_H + k);
        b[u * 2 + 0] = w.x;
        b[u * 2 + 1] = w.y;
    }
}

// ---------------------------------------------------------------------------
// NT GEMM mainloop: C(128x128,f32) += A(128xK,f16) * B(128xK,f16)^T.
// 2-stage cp.async pipeline, 1 barrier/chunk, k16-level register pipelining.
// ---------------------------------------------------------------------------
__device__ __forceinline__ void gemm_h(__half* sm,
                                       const __half* __restrict__ A, long lda,
                                       const __half* __restrict__ B, long ldb,
                                       int nchunks, float c[2][8][4]) {
    const int tid = threadIdx.x, wid = tid >> 5, lane = tid & 31;
    const int warpM = wid & 3, warpN = wid >> 2;
    const int lr = lane >> 2, lc = lane & 3;
    const uint32_t smu = (uint32_t)__cvta_generic_to_shared(sm);

    const __half* aP0 = sm + (warpM * 32 + lr) * S_H + 4 * lc;
    const __half* bP0 = sm + TILE_H + (warpN * 64 + lr) * S_H + 4 * lc;
    const __half* aP1 = aP0 + STG_H;
    const __half* bP1 = bP0 + STG_H;

    load_tile(smu, A, lda, tid);
    load_tile(smu + TILE_H * 2, B, ldb, tid);
    asm volatile("cp.async.commit_group;" ::: "memory");

    for (int i = 0; i < nchunks; ++i) {
        asm volatile("cp.async.wait_group 0;" ::: "memory");
        __syncthreads();

        const __half* aP = (i & 1) ? aP1 : aP0;
        const __half* bP = (i & 1) ? bP1 : bP0;

        // Critical path first: ks=0 fragments.
        uint32_t aA[8], bA[16], aB[8], bB[16];
        load_frags(aP, bP, 0, aA, bA);

        // Prefetch chunk i+1 (overlaps with MMAs below).
        if (i + 1 < nchunks) {
            const uint32_t s = (uint32_t)((i + 1) & 1) * STG_H * 2;
            load_tile(smu + s, A + (size_t)(i + 1) * BK, lda, tid);
            load_tile(smu + s + TILE_H * 2, B + (size_t)(i + 1) * BK, ldb, tid);
            asm volatile("cp.async.commit_group;" ::: "memory");
        }

        #pragma unroll
        for (int ks = 0; ks < 4; ++ks) {
            if (ks < 3)
                load_frags(aP, bP, ks + 1,
                           (ks & 1) ? aA : aB, (ks & 1) ? bA : bB);
            const uint32_t* a = (ks & 1) ? aB : aA;
            const uint32_t* b = (ks & 1) ? bB : bA;
            #pragma unroll
            for (int t = 0; t < 2; ++t)
                #pragma unroll
                for (int u = 0; u < 8; ++u)
                    mma16(c[t][u], a + t * 4, b + u * 2);
        }
    }
}

__device__ __forceinline__ void zero_c(float c[2][8][4]) {
    #pragma unroll
    for (int t = 0; t < 2; ++t)
        #pragma unroll
        for (int u = 0; u < 8; ++u)
            #pragma unroll
            for (int j = 0; j < 4; ++j) c[t][u][j] = 0.0f;
}

// fp32 row-major epilogue (scores, final output).
__device__ __forceinline__ void epi_store_f(float c[2][8][4], float* __restrict__ C,
                                            long ldc) {
    const int tid = threadIdx.x, wid = tid >> 5, lane = tid & 31;
    const int warpM = wid & 3, warpN = wid >> 2;
    const int lr = lane >> 2, lc = lane & 3;
    #pragma unroll
    for (int t = 0; t < 2; ++t)
        #pragma unroll
        for (int u = 0; u < 8; ++u) {
            const int r = warpM * 32 + t * 16 + lr;
            const int n = warpN * 64 + u * 8 + lc * 2;
            *(float2*)&C[(size_t)r * ldc + n]       = make_float2(c[t][u][0], c[t][u][1]);
            *(float2*)&C[(size_t)(r + 8) * ldc + n] = make_float2(c[t][u][2], c[t][u][3]);
        }
}

// fp16 row-major epilogue (Q, K).
__device__ __forceinline__ void epi_store_h(float c[2][8][4], __half* __restrict__ C,
                                            long ldc) {
    const int tid = threadIdx.x, wid = tid >> 5, lane = tid & 31;
    const int warpM = wid & 3, warpN = wid >> 2;
    const int lr = lane >> 2, lc = lane & 3;
    #pragma unroll
    for (int t = 0; t < 2; ++t)
        #pragma unroll
        for (int u = 0; u < 8; ++u) {
            const int r = warpM * 32 + t * 16 + lr;
            const int n = warpN * 64 + u * 8 + lc * 2;
            *(__half2*)&C[(size_t)r * ldc + n]       = __floats2half2_rn(c[t][u][0], c[t][u][1]);
            *(__half2*)&C[(size_t)(r + 8) * ldc + n] = __floats2half2_rn(c[t][u][2], c[t][u][3]);
        }
}

// fp16 transposed epilogue: Ct[n][m] (for V^T).
__device__ __forceinline__ void epi_store_T(float c[2][8][4], __half* __restrict__ Ct,
                                            long ldm) {
    const int tid = threadIdx.x, wid = tid >> 5, lane = tid & 31;
    const int warpM = wid & 3, warpN = wid >> 2;
    const int lr = lane >> 2, lc = lane & 3;
    #pragma unroll
    for (int t = 0; t < 2; ++t)
        #pragma unroll
        for (int u = 0; u < 8; ++u) {
            const int r = warpM * 32 + t * 16 + lr;
            const int n = warpN * 64 + u * 8 + lc * 2;
            Ct[(size_t)n * ldm + r]           = __float2half_rn(c[t][u][0]);
            Ct[(size_t)(n + 1) * ldm + r]     = __float2half_rn(c[t][u][1]);
            Ct[(size_t)n * ldm + r + 8]       = __float2half_rn(c[t][u][2]);
            Ct[(size_t)(n + 1) * ldm + r + 8] = __float2half_rn(c[t][u][3]);
        }
}

// ---------------------------------------------------------------------------
// Pre-pass kernels
// ---------------------------------------------------------------------------
__global__ __launch_bounds__(256) void roundx_kernel(const float* __restrict__ x) {
    size_t i = (size_t)blockIdx.x * blockDim.x + threadIdx.x;   // 8 elems/thread
    const float4 a = ((const float4*)x)[2 * i];
    const float4 b = ((const float4*)x)[2 * i + 1];
    __half2 h[4] = { __floats2half2_rn(a.x, a.y), __floats2half2_rn(a.z, a.w),
                     __floats2half2_rn(b.x, b.y), __floats2half2_rn(b.z, b.w) };
    ((uint4*)g_xh)[i] = *(const uint4*)h;
}

__global__ __launch_bounds__(256) void wtrans_kernel(const float* __restrict__ Wq,
                                                     const float* __restrict__ Wk,
                                                     const float* __restrict__ Wv) {
    __shared__ float t[32][33];
    const int z = blockIdx.z;
    const float* __restrict__ W = (z == 0) ? Wq : (z == 1 ? Wk : Wv);
    __half* __restrict__ O = g_wth + (size_t)z * DM * DM;
    const int tx = threadIdx.x, ty = threadIdx.y;
    const int n = blockIdx.x * 32 + tx;
    const int k0 = blockIdx.y * 32;
    for (int i = ty; i < 32; i += 8) t[i][tx] = W[(size_t)(k0 + i) * DM + n];
    __syncthreads();
    const int ko = blockIdx.y * 32 + tx;
    const int n0 = blockIdx.x * 32;
    for (int i = ty; i < 32; i += 8)
        O[(size_t)(n0 + i) * DM + ko] = __float2half_rn(t[tx][i]);
}

// ---------------------------------------------------------------------------
// GEMM 1: Q and K projections (z: 0=q, 1=k), fp16 out.
// ---------------------------------------------------------------------------
__global__ __launch_bounds__(256, 2) void qkv_qk_kernel() {
    extern __shared__ __half smh[];
    const int z = blockIdx.z;
    const long m0 = (long)blockIdx.y * BM;
    const long n0 = (long)blockIdx.x * BN;
    const __half* A = g_xh + (size_t)m0 * DM;
    const __half* B = g_wth + (size_t)z * DM * DM + (size_t)n0 * DM;

    float c[2][8][4];
    zero_c(c);
    gemm_h(smh, A, DM, B, DM, DM / BK, c);

    __half* C = (z == 0 ? g_qh : g_kh) + (size_t)m0 * DM + n0;
    epi_store_h(c, C, DM);
}

// ---------------------------------------------------------------------------
// GEMM 2 (merged): ids [0,544): S = Q@K^T lower-tri tiles (fp32 out).
//                  ids [544,1056): V-projection -> V^T (fp16 out).
// ---------------------------------------------------------------------------
__global__ __launch_bounds__(256, 2) void scorev_kernel() {
    extern __shared__ __half smh[];
    const int id = blockIdx.x;
    float c[2][8][4];
    zero_c(c);

    if (id < 544) {
        const int b = id / 136;
        const int tt = id - b * 136;
        int by = (int)((sqrtf(8.0f * tt + 1.0f) - 1.0f) * 0.5f);
        while ((by + 1) * (by + 2) / 2 <= tt) ++by;
        while (by * (by + 1) / 2 > tt) --by;
        const int bx = tt - by * (by + 1) / 2;

        const long m0 = (long)by * BM;
        const long n0 = (long)bx * BN;
        const __half* A = g_qh + ((size_t)b * SEQ + m0) * DM;
        const __half* B = g_kh + ((size_t)b * SEQ + n0) * DM;

        gemm_h(smh, A, DM, B, DM, DM / BK, c);

        float* C = g_s + ((size_t)b * SEQ + m0) * SEQ + n0;
        epi_store_f(c, C, SEQ);
    } else {
        const int r = id - 544;
        const long n0 = (long)(r & 7) * BN;
        const long m0 = (long)(r >> 3) * BM;
        const __half* A = g_xh + (size_t)m0 * DM;
        const __half* B = g_wth + (size_t)2 * DM * DM + (size_t)n0 * DM;

        gemm_h(smh, A, DM, B, DM, DM / BK, c);

        const int b = (int)(m0 / SEQ);
        const long mloc = m0 - (long)b * SEQ;
        __half* Ct = g_vth + ((size_t)b * DM + n0) * SEQ + mloc;
        epi_store_T(c, Ct, SEQ);
    }
}

// ---------------------------------------------------------------------------
// Softmax (causal, single pass, row in registers). Reads fp32 scores,
// writes fp16 probs; zeroes to the 128-tile boundary for PV.
// ---------------------------------------------------------------------------
__global__ __launch_bounds__(256) void softmax_kernel() {
    const int row = blockIdx.x;
    const int b = row >> 11;
    const int q = row & (SEQ - 1);
    const float* __restrict__ S = g_s + (size_t)b * SEQ * SEQ + (size_t)q * SEQ;
    __half* __restrict__ P = g_ph + (size_t)b * SEQ * SEQ + (size_t)q * SEQ;
    const int nvalid = q + 1;
    const int nzero = ((q >> 7) + 1) << 7;
    const int tid = threadIdx.x, wid = tid >> 5, lane = tid & 31;

    __shared__ float red[8];

    float v[8];
    float lmax = -CUDART_INF_F;
    #pragma unroll
    for (int j = 0; j < 8; ++j) {
        const int col = j * 256 + tid;
        if (col < nvalid) {
            v[j] = S[col] * SCALE;
            lmax = fmaxf(lmax, v[j]);
        }
    }
    #pragma unroll
    for (int o = 16; o > 0; o >>= 1)
        lmax = fmaxf(lmax, __shfl_xor_sync(0xFFFFFFFFu, lmax, o));
    if (lane == 0) red[wid] = lmax;
    __syncthreads();
    float rmax = red[0];
    #pragma unroll
    for (int w = 1; w < 8; ++w) rmax = fmaxf(rmax, red[w]);
    __syncthreads();

    float lsum = 0.0f;
    #pragma unroll
    for (int j = 0; j < 8; ++j) {
        const int col = j * 256 + tid;
        if (col < nvalid) {
            v[j] = __expf(v[j] - rmax);
            lsum += v[j];
        }
    }
    #pragma unroll
    for (int o = 16; o > 0; o >>= 1)
        lsum += __shfl_xor_sync(0xFFFFFFFFu, lsum, o);
    if (lane == 0) red[wid] = lsum;
    __syncthreads();
    float rsum = red[0];
    #pragma unroll
    for (int w = 1; w < 8; ++w) rsum += red[w];
    const float inv = 1.0f / rsum;

    #pragma unroll
    for (int j = 0; j < 8; ++j) {
        const int col = j * 256 + tid;
        if (col < nzero)
            P[col] = __float2half_rn((col < nvalid) ? v[j] * inv : 0.0f);
    }
}

// ---------------------------------------------------------------------------
// GEMM 3: O = P @ V  (A = P fp16, B = V^T fp16), K truncated at causal edge.
// Heavy tiles first for wave balance.
// ---------------------------------------------------------------------------
__global__ __launch_bounds__(256, 2) void pv_tc_kernel(float* __restrict__ out) {
    extern __shared__ __half smh[];
    const int b = blockIdx.z;
    const long m0 = (long)(gridDim.y - 1 - blockIdx.y) * BM;   // heavy-first
    const long n0 = (long)blockIdx.x * BN;
    const __half* A = g_ph + ((size_t)b * SEQ + m0) * SEQ;
    const __half* B = g_vth + ((size_t)b * DM + n0) * SEQ;
    const int nchunks = (int)((m0 + BM) / BK);

    float c[2][8][4];
    zero_c(c);
    gemm_h(smh, A, SEQ, B, SEQ, nchunks, c);

    float* C = out + ((size_t)b * SEQ + m0) * DM + n0;
    epi_store_f(c, C, DM);
}

// ---------------------------------------------------------------------------
extern "C" void kernel_launch(void* const* d_in, const int* in_sizes, int n_in,
                              void* d_out, int out_size) {
    (void)in_sizes; (void)n_in; (void)out_size;
    const float* x  = (const float*)d_in[0];
    const float* Wq = (const float*)d_in[1];
    const float* Wk = (const float*)d_in[2];
    const float* Wv = (const float*)d_in[3];
    float* out = (float*)d_out;

    cudaFuncSetAttribute(qkv_qk_kernel, cudaFuncAttributeMaxDynamicSharedMemorySize, SMEM_BYTES);
    cudaFuncSetAttribute(scorev_kernel, cudaFuncAttributeMaxDynamicSharedMemorySize, SMEM_BYTES);
    cudaFuncSetAttribute(pv_tc_kernel,  cudaFuncAttributeMaxDynamicSharedMemorySize, SMEM_BYTES);

    roundx_kernel<<<(MROWS * DM / 8) / 256, 256>>>(x);
    {
        dim3 g(DM / 32, DM / 32, 3);
        dim3 blk(32, 8);
        wtrans_kernel<<<g, blk>>>(Wq, Wk, Wv);
    }
    {
        dim3 g(DM / BN, MROWS / BM, 2);              // 8 x 64 x 2 (Q, K)
        qkv_qk_kernel<<<g, 256, SMEM_BYTES>>>();
    }
    scorev_kernel<<<1056, 256, SMEM_BYTES>>>();      // 544 score + 512 V-proj
    softmax_kernel<<<BATCH * SEQ, 256>>>();
    {
        dim3 g(DM / BN, SEQ / BM, BATCH);            // 8 x 16 x 4
        pv_tc_kernel<<<g, 256, SMEM_BYTES>>>(out);
    }
}

// round 11
// speedup vs baseline: 8.1848x; 1.0830x over previous
#include <cuda_runtime.h>
#include <cuda_fp16.h>
#include <cstdint>
#include <math_constants.h>

#define BATCH 4
#define SEQ   2048
#define DM    1024
#define MROWS (BATCH * SEQ)
#define SCALE (1.0f / 32.0f)

// GEMM tiling (fp16 operands, fp32 accum)
#define BM 128
#define BN 128
#define BK 64
#define S_H 80                        // row stride in fp16 (64 + 16 pad)
#define TILE_H (BM * S_H)             // 10240 halfs per tile (20480 B)
#define STG_H  (2 * TILE_H)           // A+B per stage
#define SMEM_BYTES (2 * STG_H * 2)    // 81920 B (2 stages)

// Scratch (__device__ globals; allocation-free rule)
__device__ __half g_xh [(size_t)MROWS * DM];         // x   (fp16)
__device__ __half g_wh [(size_t)3 * DM * DM];        // slot0: Wq, slot1: Wk (row-major);
                                                     // slot2: Wv^T
__device__ __half g_mth[(size_t)DM * DM];            // (Wq Wk^T)^T  (fp16)
__device__ __half g_th [(size_t)MROWS * DM];         // T = x (Wq Wk^T)  (fp16)
__device__ __half g_vth[(size_t)MROWS * DM];         // V^T per batch [b][d][key]
__device__ float  g_s  [(size_t)BATCH * SEQ * SEQ];  // scores (fp32)
__device__ __half g_ph [(size_t)BATCH * SEQ * SEQ];  // probs  (fp16)

// ---------------------------------------------------------------------------
__device__ __forceinline__ void cp16(uint32_t dst, const void* src) {
    asm volatile("cp.async.cg.shared.global [%0], [%1], 16;"
                 :: "r"(dst), "l"(src) : "memory");
}

__device__ __forceinline__ void mma16(float* c, const uint32_t* a, const uint32_t* b) {
    asm volatile(
        "mma.sync.aligned.m16n8k16.row.col.f32.f16.f16.f32 "
        "{%0,%1,%2,%3}, {%4,%5,%6,%7}, {%8,%9}, {%0,%1,%2,%3};"
        : "+f"(c[0]), "+f"(c[1]), "+f"(c[2]), "+f"(c[3])
        : "r"(a[0]), "r"(a[1]), "r"(a[2]), "r"(a[3]), "r"(b[0]), "r"(b[1]));
}

// Issue cp.async for a 128x64-fp16 K-major tile into padded SMEM.
__device__ __forceinline__ void load_tile(uint32_t smbase_b, const __half* __restrict__ src,
                                          long ld, int tid) {
    #pragma unroll
    for (int i = 0; i < 4; ++i) {
        int idx = i * 256 + tid;
        int row = idx >> 3, c8 = idx & 7;
        cp16(smbase_b + (uint32_t)(row * (S_H * 2) + c8 * 16),
             src + (size_t)row * ld + c8 * 8);
    }
}

// Load one k16-step of fragments via LDS.64, immediate offsets.
// k-permutation: quad-lane lc reads physical cols 4lc..4lc+3 as logical
// {2lc, 2lc+1, 2lc+8, 2lc+9}; A and B agree, so the k-sum is unchanged.
__device__ __forceinline__ void load_frags(const __half* __restrict__ aP,
                                           const __half* __restrict__ bP,
                                           int ks, uint32_t* a, uint32_t* b) {
    const int k = ks * 16;
    const uint2 u0 = *(const uint2*)(aP + k);               // t=0 row lr
    const uint2 u1 = *(const uint2*)(aP + 8 * S_H + k);     // t=0 row lr+8
    const uint2 u2 = *(const uint2*)(aP + 16 * S_H + k);    // t=1 row lr
    const uint2 u3 = *(const uint2*)(aP + 24 * S_H + k);    // t=1 row lr+8
    a[0] = u0.x; a[1] = u1.x; a[2] = u0.y; a[3] = u1.y;
    a[4] = u2.x; a[5] = u3.x; a[6] = u2.y; a[7] = u3.y;
    #pragma unroll
    for (int u = 0; u < 8; ++u) {
        const uint2 w = *(const uint2*)(bP + u * 8 * S_H + k);
        b[u * 2 + 0] = w.x;
        b[u * 2 + 1] = w.y;
    }
}

// ---------------------------------------------------------------------------
// NT GEMM mainloop: C(128x128,f32) += A(128xK,f16) * B(128xK,f16)^T.
// 2-stage cp.async pipeline, 1 barrier/chunk, k16-level register pipelining.
// ---------------------------------------------------------------------------
__device__ __forceinline__ void gemm_h(__half* sm,
                                       const __half* __restrict__ A, long lda,
                                       const __half* __restrict__ B, long ldb,
                                       int nchunks, float c[2][8][4]) {
    const int tid = threadIdx.x, wid = tid >> 5, lane = tid & 31;
    const int warpM = wid & 3, warpN = wid >> 2;
    const int lr = lane >> 2, lc = lane & 3;
    const uint32_t smu = (uint32_t)__cvta_generic_to_shared(sm);

    const __half* aP0 = sm + (warpM * 32 + lr) * S_H + 4 * lc;
    const __half* bP0 = sm + TILE_H + (warpN * 64 + lr) * S_H + 4 * lc;
    const __half* aP1 = aP0 + STG_H;
    const __half* bP1 = bP0 + STG_H;

    load_tile(smu, A, lda, tid);
    load_tile(smu + TILE_H * 2, B, ldb, tid);
    asm volatile("cp.async.commit_group;" ::: "memory");

    for (int i = 0; i < nchunks; ++i) {
        asm volatile("cp.async.wait_group 0;" ::: "memory");
        __syncthreads();

        const __half* aP = (i & 1) ? aP1 : aP0;
        const __half* bP = (i & 1) ? bP1 : bP0;

        // Critical path first: ks=0 fragments.
        uint32_t aA[8], bA[16], aB[8], bB[16];
        load_frags(aP, bP, 0, aA, bA);

        // Prefetch chunk i+1 (overlaps with MMAs below).
        if (i + 1 < nchunks) {
            const uint32_t s = (uint32_t)((i + 1) & 1) * STG_H * 2;
            load_tile(smu + s, A + (size_t)(i + 1) * BK, lda, tid);
            load_tile(smu + s + TILE_H * 2, B + (size_t)(i + 1) * BK, ldb, tid);
            asm volatile("cp.async.commit_group;" ::: "memory");
        }

        #pragma unroll
        for (int ks = 0; ks < 4; ++ks) {
            if (ks < 3)
                load_frags(aP, bP, ks + 1,
                           (ks & 1) ? aA : aB, (ks & 1) ? bA : bB);
            const uint32_t* a = (ks & 1) ? aB : aA;
            const uint32_t* b = (ks & 1) ? bB : bA;
            #pragma unroll
            for (int t = 0; t < 2; ++t)
                #pragma unroll
                for (int u = 0; u < 8; ++u)
                    mma16(c[t][u], a + t * 4, b + u * 2);
        }
    }
}

__device__ __forceinline__ void zero_c(float c[2][8][4]) {
    #pragma unroll
    for (int t = 0; t < 2; ++t)
        #pragma unroll
        for (int u = 0; u < 8; ++u)
            #pragma unroll
            for (int j = 0; j < 4; ++j) c[t][u][j] = 0.0f;
}

// fp32 row-major epilogue (scores, final output).
__device__ __forceinline__ void epi_store_f(float c[2][8][4], float* __restrict__ C,
                                            long ldc) {
    const int tid = threadIdx.x, wid = tid >> 5, lane = tid & 31;
    const int warpM = wid & 3, warpN = wid >> 2;
    const int lr = lane >> 2, lc = lane & 3;
    #pragma unroll
    for (int t = 0; t < 2; ++t)
        #pragma unroll
        for (int u = 0; u < 8; ++u) {
            const int r = warpM * 32 + t * 16 + lr;
            const int n = warpN * 64 + u * 8 + lc * 2;
            *(float2*)&C[(size_t)r * ldc + n]       = make_float2(c[t][u][0], c[t][u][1]);
            *(float2*)&C[(size_t)(r + 8) * ldc + n] = make_float2(c[t][u][2], c[t][u][3]);
        }
}

// fp16 row-major epilogue (T).
__device__ __forceinline__ void epi_store_h(float c[2][8][4], __half* __restrict__ C,
                                            long ldc) {
    const int tid = threadIdx.x, wid = tid >> 5, lane = tid & 31;
    const int warpM = wid & 3, warpN = wid >> 2;
    const int lr = lane >> 2, lc = lane & 3;
    #pragma unroll
    for (int t = 0; t < 2; ++t)
        #pragma unroll
        for (int u = 0; u < 8; ++u) {
            const int r = warpM * 32 + t * 16 + lr;
            const int n = warpN * 64 + u * 8 + lc * 2;
            *(__half2*)&C[(size_t)r * ldc + n]       = __floats2half2_rn(c[t][u][0], c[t][u][1]);
            *(__half2*)&C[(size_t)(r + 8) * ldc + n] = __floats2half2_rn(c[t][u][2], c[t][u][3]);
        }
}

// fp16 transposed epilogue: Ct[n][m] (for V^T and M^T).
__device__ __forceinline__ void epi_store_T(float c[2][8][4], __half* __restrict__ Ct,
                                            long ldm) {
    const int tid = threadIdx.x, wid = tid >> 5, lane = tid & 31;
    const int warpM = wid & 3, warpN = wid >> 2;
    const int lr = lane >> 2, lc = lane & 3;
    #pragma unroll
    for (int t = 0; t < 2; ++t)
        #pragma unroll
        for (int u = 0; u < 8; ++u) {
            const int r = warpM * 32 + t * 16 + lr;
            const int n = warpN * 64 + u * 8 + lc * 2;
            Ct[(size_t)n * ldm + r]           = __float2half_rn(c[t][u][0]);
            Ct[(size_t)(n + 1) * ldm + r]     = __float2half_rn(c[t][u][1]);
            Ct[(size_t)n * ldm + r + 8]       = __float2half_rn(c[t][u][2]);
            Ct[(size_t)(n + 1) * ldm + r + 8] = __float2half_rn(c[t][u][3]);
        }
}

// ---------------------------------------------------------------------------
// Pre-pass kernels
// ---------------------------------------------------------------------------
__global__ __launch_bounds__(256) void roundx_kernel(const float* __restrict__ x) {
    size_t i = (size_t)blockIdx.x * blockDim.x + threadIdx.x;   // 8 elems/thread
    const float4 a = ((const float4*)x)[2 * i];
    const float4 b = ((const float4*)x)[2 * i + 1];
    __half2 h[4] = { __floats2half2_rn(a.x, a.y), __floats2half2_rn(a.z, a.w),
                     __floats2half2_rn(b.x, b.y), __floats2half2_rn(b.z, b.w) };
    ((uint4*)g_xh)[i] = *(const uint4*)h;
}

// Elementwise fp16 rounding of Wq (z=0) and Wk (z=1), layout preserved.
__global__ __launch_bounds__(256) void roundw_kernel(const float* __restrict__ Wq,
                                                     const float* __restrict__ Wk) {
    const int z = blockIdx.y;
    const float* __restrict__ W = z ? Wk : Wq;
    __half* __restrict__ O = g_wh + (size_t)z * DM * DM;
    size_t i = (size_t)blockIdx.x * blockDim.x + threadIdx.x;   // 8 elems/thread
    const float4 a = ((const float4*)W)[2 * i];
    const float4 b = ((const float4*)W)[2 * i + 1];
    __half2 h[4] = { __floats2half2_rn(a.x, a.y), __floats2half2_rn(a.z, a.w),
                     __floats2half2_rn(b.x, b.y), __floats2half2_rn(b.z, b.w) };
    ((uint4*)O)[i] = *(const uint4*)h;
}

// Transpose+round Wv into slot 2 of g_wh.
__global__ __launch_bounds__(256) void wtrans_kernel(const float* __restrict__ Wv) {
    __shared__ float t[32][33];
    __half* __restrict__ O = g_wh + (size_t)2 * DM * DM;
    const int tx = threadIdx.x, ty = threadIdx.y;
    const int n = blockIdx.x * 32 + tx;
    const int k0 = blockIdx.y * 32;
    for (int i = ty; i < 32; i += 8) t[i][tx] = Wv[(size_t)(k0 + i) * DM + n];
    __syncthreads();
    const int ko = blockIdx.y * 32 + tx;
    const int n0 = blockIdx.x * 32;
    for (int i = ty; i < 32; i += 8)
        O[(size_t)(n0 + i) * DM + ko] = __float2half_rn(t[tx][i]);
}

// ---------------------------------------------------------------------------
// GEMM 0: M = Wq @ Wk^T (contraction over d_out), stored transposed (M^T).
// ---------------------------------------------------------------------------
__global__ __launch_bounds__(256, 2) void m_kernel() {
    extern __shared__ __half smh[];
    const long m0 = (long)(blockIdx.x >> 3) * BM;   // Wq row (d_in_q)
    const long n0 = (long)(blockIdx.x & 7) * BN;    // Wk row (d_in_k)
    const __half* A = g_wh + (size_t)m0 * DM;                    // Wq
    const __half* B = g_wh + (size_t)DM * DM + (size_t)n0 * DM;  // Wk

    float c[2][8][4];
    zero_c(c);
    gemm_h(smh, A, DM, B, DM, DM / BK, c);

    // g_mth[j][i] = M[i][j]
    epi_store_T(c, g_mth + (size_t)n0 * DM + m0, DM);
}

// ---------------------------------------------------------------------------
// GEMM 1 (merged): ids [0,512): T = x @ M     (via NT against M^T), fp16 out.
//                  ids [512,1024): V-projection -> V^T, fp16 out.
// ---------------------------------------------------------------------------
__global__ __launch_bounds__(256, 2) void tv_kernel() {
    extern __shared__ __half smh[];
    const int id = blockIdx.x;
    float c[2][8][4];
    zero_c(c);

    if (id < 512) {
        const long m0 = (long)(id >> 3) * BM;
        const long n0 = (long)(id & 7) * BN;
        const __half* A = g_xh + (size_t)m0 * DM;
        const __half* B = g_mth + (size_t)n0 * DM;

        gemm_h(smh, A, DM, B, DM, DM / BK, c);

        epi_store_h(c, g_th + (size_t)m0 * DM + n0, DM);
    } else {
        const int r = id - 512;
        const long n0 = (long)(r & 7) * BN;
        const long m0 = (long)(r >> 3) * BM;
        const __half* A = g_xh + (size_t)m0 * DM;
        const __half* B = g_wh + (size_t)2 * DM * DM + (size_t)n0 * DM;

        gemm_h(smh, A, DM, B, DM, DM / BK, c);

        const int b = (int)(m0 / SEQ);
        const long mloc = m0 - (long)b * SEQ;
        __half* Ct = g_vth + ((size_t)b * DM + n0) * SEQ + mloc;
        epi_store_T(c, Ct, SEQ);
    }
}

// ---------------------------------------------------------------------------
// GEMM 2: S = T @ x^T per batch, lower-triangular tiles only (fp32 out).
// ---------------------------------------------------------------------------
__global__ __launch_bounds__(256, 2) void score_kernel() {
    extern __shared__ __half smh[];
    const int id = blockIdx.x;
    const int b = id / 136;
    const int tt = id - b * 136;
    int by = (int)((sqrtf(8.0f * tt + 1.0f) - 1.0f) * 0.5f);
    while ((by + 1) * (by + 2) / 2 <= tt) ++by;
    while (by * (by + 1) / 2 > tt) --by;
    const int bx = tt - by * (by + 1) / 2;

    const long m0 = (long)by * BM;
    const long n0 = (long)bx * BN;
    const __half* A = g_th + ((size_t)b * SEQ + m0) * DM;
    const __half* B = g_xh + ((size_t)b * SEQ + n0) * DM;

    float c[2][8][4];
    zero_c(c);
    gemm_h(smh, A, DM, B, DM, DM / BK, c);

    float* C = g_s + ((size_t)b * SEQ + m0) * SEQ + n0;
    epi_store_f(c, C, SEQ);
}

// ---------------------------------------------------------------------------
// Softmax (causal, single pass, row in registers). Reads fp32 scores,
// writes fp16 probs; zeroes to the 128-tile boundary for PV.
// ---------------------------------------------------------------------------
__global__ __launch_bounds__(256) void softmax_kernel() {
    const int row = blockIdx.x;
    const int b = row >> 11;
    const int q = row & (SEQ - 1);
    const float* __restrict__ S = g_s + (size_t)b * SEQ * SEQ + (size_t)q * SEQ;
    __half* __restrict__ P = g_ph + (size_t)b * SEQ * SEQ + (size_t)q * SEQ;
    const int nvalid = q + 1;
    const int nzero = ((q >> 7) + 1) << 7;
    const int tid = threadIdx.x, wid = tid >> 5, lane = tid & 31;

    __shared__ float red[8];

    float v[8];
    float lmax = -CUDART_INF_F;
    #pragma unroll
    for (int j = 0; j < 8; ++j) {
        const int col = j * 256 + tid;
        if (col < nvalid) {
            v[j] = S[col] * SCALE;
            lmax = fmaxf(lmax, v[j]);
        }
    }
    #pragma unroll
    for (int o = 16; o > 0; o >>= 1)
        lmax = fmaxf(lmax, __shfl_xor_sync(0xFFFFFFFFu, lmax, o));
    if (lane == 0) red[wid] = lmax;
    __syncthreads();
    float rmax = red[0];
    #pragma unroll
    for (int w = 1; w < 8; ++w) rmax = fmaxf(rmax, red[w]);
    __syncthreads();

    float lsum = 0.0f;
    #pragma unroll
    for (int j = 0; j < 8; ++j) {
        const int col = j * 256 + tid;
        if (col < nvalid) {
            v[j] = __expf(v[j] - rmax);
            lsum += v[j];
        }
    }
    #pragma unroll
    for (int o = 16; o > 0; o >>= 1)
        lsum += __shfl_xor_sync(0xFFFFFFFFu, lsum, o);
    if (lane == 0) red[wid] = lsum;
    __syncthreads();
    float rsum = red[0];
    #pragma unroll
    for (int w = 1; w < 8; ++w) rsum += red[w];
    const float inv = 1.0f / rsum;

    #pragma unroll
    for (int j = 0; j < 8; ++j) {
        const int col = j * 256 + tid;
        if (col < nzero)
            P[col] = __float2half_rn((col < nvalid) ? v[j] * inv : 0.0f);
    }
}

// ---------------------------------------------------------------------------
// GEMM 3: O = P @ V  (A = P fp16, B = V^T fp16), K truncated at causal edge.
// Heavy tiles first for wave balance.
// ---------------------------------------------------------------------------
__global__ __launch_bounds__(256, 2) void pv_tc_kernel(float* __restrict__ out) {
    extern __shared__ __half smh[];
    const int b = blockIdx.z;
    const long m0 = (long)(gridDim.y - 1 - blockIdx.y) * BM;   // heavy-first
    const long n0 = (long)blockIdx.x * BN;
    const __half* A = g_ph + ((size_t)b * SEQ + m0) * SEQ;
    const __half* B = g_vth + ((size_t)b * DM + n0) * SEQ;
    const int nchunks = (int)((m0 + BM) / BK);

    float c[2][8][4];
    zero_c(c);
    gemm_h(smh, A, SEQ, B, SEQ, nchunks, c);

    float* C = out + ((size_t)b * SEQ + m0) * DM + n0;
    epi_store_f(c, C, DM);
}

// ---------------------------------------------------------------------------
extern "C" void kernel_launch(void* const* d_in, const int* in_sizes, int n_in,
                              void* d_out, int out_size) {
    (void)in_sizes; (void)n_in; (void)out_size;
    const float* x  = (const float*)d_in[0];
    const float* Wq = (const float*)d_in[1];
    const float* Wk = (const float*)d_in[2];
    const float* Wv = (const float*)d_in[3];
    float* out = (float*)d_out;

    cudaFuncSetAttribute(m_kernel,     cudaFuncAttributeMaxDynamicSharedMemorySize, SMEM_BYTES);
    cudaFuncSetAttribute(tv_kernel,    cudaFuncAttributeMaxDynamicSharedMemorySize, SMEM_BYTES);
    cudaFuncSetAttribute(score_kernel, cudaFuncAttributeMaxDynamicSharedMemorySize, SMEM_BYTES);
    cudaFuncSetAttribute(pv_tc_kernel, cudaFuncAttributeMaxDynamicSharedMemorySize, SMEM_BYTES);

    roundx_kernel<<<(MROWS * DM / 8) / 256, 256>>>(x);
    {
        dim3 g((DM * DM / 8) / 256, 2);
        roundw_kernel<<<g, 256>>>(Wq, Wk);
    }
    {
        dim3 g(DM / 32, DM / 32);
        dim3 blk(32, 8);
        wtrans_kernel<<<g, blk>>>(Wv);
    }
    m_kernel<<<64, 256, SMEM_BYTES>>>();             // M = Wq Wk^T (tiny)
    tv_kernel<<<1024, 256, SMEM_BYTES>>>();          // 512 T + 512 V-proj
    score_kernel<<<544, 256, SMEM_BYTES>>>();        // triangular S = T x^T
    softmax_kernel<<<BATCH * SEQ, 256>>>();
    {
        dim3 g(DM / BN, SEQ / BM, BATCH);            // 8 x 16 x 4
        pv_tc_kernel<<<g, 256, SMEM_BYTES>>>(out);
    }
}

// round 12
// speedup vs baseline: 8.3685x; 1.0224x over previous
#include <cuda_runtime.h>
#include <cuda_fp16.h>
#include <cstdint>
#include <math_constants.h>

#define BATCH 4
#define SEQ   2048
#define DM    1024
#define MROWS (BATCH * SEQ)
#define SCALE (1.0f / 32.0f)

// GEMM tiling (fp16 operands, fp32 accum)
#define BM 128
#define BN 128
#define BK 64
#define S_H 80                        // row stride in fp16 (64 + 16 pad)
#define TILE_H (BM * S_H)             // 10240 halfs per tile (20480 B)
#define STG_H  (2 * TILE_H)           // A+B per stage
#define SMEM_BYTES (2 * STG_H * 2)    // 81920 B (2 stages)

// Scratch (__device__ globals; allocation-free rule)
__device__ __half g_xh [(size_t)MROWS * DM];         // x   (fp16)
__device__ __half g_wh [(size_t)3 * DM * DM];        // slot0: Wq, slot1: Wk (row-major);
                                                     // slot2: Wv^T
__device__ __half g_mth[(size_t)DM * DM];            // (Wq Wk^T / 32)^T  (fp16)
__device__ __half g_th [(size_t)MROWS * DM];         // T = x (Wq Wk^T / 32)  (fp16)
__device__ __half g_vth[(size_t)MROWS * DM];         // V^T per batch [b][d][key]
__device__ __half g_ph [(size_t)BATCH * SEQ * SEQ];  // scores -> probs (fp16, in place)

// ---------------------------------------------------------------------------
__device__ __forceinline__ void cp16(uint32_t dst, const void* src) {
    asm volatile("cp.async.cg.shared.global [%0], [%1], 16;"
                 :: "r"(dst), "l"(src) : "memory");
}

__device__ __forceinline__ void mma16(float* c, const uint32_t* a, const uint32_t* b) {
    asm volatile(
        "mma.sync.aligned.m16n8k16.row.col.f32.f16.f16.f32 "
        "{%0,%1,%2,%3}, {%4,%5,%6,%7}, {%8,%9}, {%0,%1,%2,%3};"
        : "+f"(c[0]), "+f"(c[1]), "+f"(c[2]), "+f"(c[3])
        : "r"(a[0]), "r"(a[1]), "r"(a[2]), "r"(a[3]), "r"(b[0]), "r"(b[1]));
}

// Issue cp.async for a 128x64-fp16 K-major tile into padded SMEM.
__device__ __forceinline__ void load_tile(uint32_t smbase_b, const __half* __restrict__ src,
                                          long ld, int tid) {
    #pragma unroll
    for (int i = 0; i < 4; ++i) {
        int idx = i * 256 + tid;
        int row = idx >> 3, c8 = idx & 7;
        cp16(smbase_b + (uint32_t)(row * (S_H * 2) + c8 * 16),
             src + (size_t)row * ld + c8 * 8);
    }
}

// Load one k16-step of fragments via LDS.64, immediate offsets.
// k-permutation: quad-lane lc reads physical cols 4lc..4lc+3 as logical
// {2lc, 2lc+1, 2lc+8, 2lc+9}; A and B agree, so the k-sum is unchanged.
__device__ __forceinline__ void load_frags(const __half* __restrict__ aP,
                                           const __half* __restrict__ bP,
                                           int ks, uint32_t* a, uint32_t* b) {
    const int k = ks * 16;
    const uint2 u0 = *(const uint2*)(aP + k);               // t=0 row lr
    const uint2 u1 = *(const uint2*)(aP + 8 * S_H + k);     // t=0 row lr+8
    const uint2 u2 = *(const uint2*)(aP + 16 * S_H + k);    // t=1 row lr
    const uint2 u3 = *(const uint2*)(aP + 24 * S_H + k);    // t=1 row lr+8
    a[0] = u0.x; a[1] = u1.x; a[2] = u0.y; a[3] = u1.y;
    a[4] = u2.x; a[5] = u3.x; a[6] = u2.y; a[7] = u3.y;
    #pragma unroll
    for (int u = 0; u < 8; ++u) {
        const uint2 w = *(const uint2*)(bP + u * 8 * S_H + k);
        b[u * 2 + 0] = w.x;
        b[u * 2 + 1] = w.y;
    }
}

// ---------------------------------------------------------------------------
// NT GEMM mainloop: C(128x128,f32) += A(128xK,f16) * B(128xK,f16)^T.
// 2-stage cp.async pipeline, 1 barrier/chunk, k16-level register pipelining.
// ---------------------------------------------------------------------------
__device__ __forceinline__ void gemm_h(__half* sm,
                                       const __half* __restrict__ A, long lda,
                                       const __half* __restrict__ B, long ldb,
                                       int nchunks, float c[2][8][4]) {
    const int tid = threadIdx.x, wid = tid >> 5, lane = tid & 31;
    const int warpM = wid & 3, warpN = wid >> 2;
    const int lr = lane >> 2, lc = lane & 3;
    const uint32_t smu = (uint32_t)__cvta_generic_to_shared(sm);

    const __half* aP0 = sm + (warpM * 32 + lr) * S_H + 4 * lc;
    const __half* bP0 = sm + TILE_H + (warpN * 64 + lr) * S_H + 4 * lc;
    const __half* aP1 = aP0 + STG_H;
    const __half* bP1 = bP0 + STG_H;

    load_tile(smu, A, lda, tid);
    load_tile(smu + TILE_H * 2, B, ldb, tid);
    asm volatile("cp.async.commit_group;" ::: "memory");

    for (int i = 0; i < nchunks; ++i) {
        asm volatile("cp.async.wait_group 0;" ::: "memory");
        __syncthreads();

        const __half* aP = (i & 1) ? aP1 : aP0;
        const __half* bP = (i & 1) ? bP1 : bP0;

        // Critical path first: ks=0 fragments.
        uint32_t aA[8], bA[16], aB[8], bB[16];
        load_frags(aP, bP, 0, aA, bA);

        // Prefetch chunk i+1 (overlaps with MMAs below).
        if (i + 1 < nchunks) {
            const uint32_t s = (uint32_t)((i + 1) & 1) * STG_H * 2;
            load_tile(smu + s, A + (size_t)(i + 1) * BK, lda, tid);
            load_tile(smu + s + TILE_H * 2, B + (size_t)(i + 1) * BK, ldb, tid);
            asm volatile("cp.async.commit_group;" ::: "memory");
        }

        #pragma unroll
        for (int ks = 0; ks < 4; ++ks) {
            if (ks < 3)
                load_frags(aP, bP, ks + 1,
                           (ks & 1) ? aA : aB, (ks & 1) ? bA : bB);
            const uint32_t* a = (ks & 1) ? aB : aA;
            const uint32_t* b = (ks & 1) ? bB : bA;
            #pragma unroll
            for (int t = 0; t < 2; ++t)
                #pragma unroll
                for (int u = 0; u < 8; ++u)
                    mma16(c[t][u], a + t * 4, b + u * 2);
        }
    }
}

__device__ __forceinline__ void zero_c(float c[2][8][4]) {
    #pragma unroll
    for (int t = 0; t < 2; ++t)
        #pragma unroll
        for (int u = 0; u < 8; ++u)
            #pragma unroll
            for (int j = 0; j < 4; ++j) c[t][u][j] = 0.0f;
}

// fp32 row-major epilogue (final output).
__device__ __forceinline__ void epi_store_f(float c[2][8][4], float* __restrict__ C,
                                            long ldc) {
    const int tid = threadIdx.x, wid = tid >> 5, lane = tid & 31;
    const int warpM = wid & 3, warpN = wid >> 2;
    const int lr = lane >> 2, lc = lane & 3;
    #pragma unroll
    for (int t = 0; t < 2; ++t)
        #pragma unroll
        for (int u = 0; u < 8; ++u) {
            const int r = warpM * 32 + t * 16 + lr;
            const int n = warpN * 64 + u * 8 + lc * 2;
            *(float2*)&C[(size_t)r * ldc + n]       = make_float2(c[t][u][0], c[t][u][1]);
            *(float2*)&C[(size_t)(r + 8) * ldc + n] = make_float2(c[t][u][2], c[t][u][3]);
        }
}

// fp16 row-major epilogue (T, scores).
__device__ __forceinline__ void epi_store_h(float c[2][8][4], __half* __restrict__ C,
                                            long ldc) {
    const int tid = threadIdx.x, wid = tid >> 5, lane = tid & 31;
    const int warpM = wid & 3, warpN = wid >> 2;
    const int lr = lane >> 2, lc = lane & 3;
    #pragma unroll
    for (int t = 0; t < 2; ++t)
        #pragma unroll
        for (int u = 0; u < 8; ++u) {
            const int r = warpM * 32 + t * 16 + lr;
            const int n = warpN * 64 + u * 8 + lc * 2;
            *(__half2*)&C[(size_t)r * ldc + n]       = __floats2half2_rn(c[t][u][0], c[t][u][1]);
            *(__half2*)&C[(size_t)(r + 8) * ldc + n] = __floats2half2_rn(c[t][u][2], c[t][u][3]);
        }
}

// fp16 transposed epilogue with scale: Ct[n][m] (for V^T and M^T).
__device__ __forceinline__ void epi_store_T(float c[2][8][4], __half* __restrict__ Ct,
                                            long ldm, float scl) {
    const int tid = threadIdx.x, wid = tid >> 5, lane = tid & 31;
    const int warpM = wid & 3, warpN = wid >> 2;
    const int lr = lane >> 2, lc = lane & 3;
    #pragma unroll
    for (int t = 0; t < 2; ++t)
        #pragma unroll
        for (int u = 0; u < 8; ++u) {
            const int r = warpM * 32 + t * 16 + lr;
            const int n = warpN * 64 + u * 8 + lc * 2;
            Ct[(size_t)n * ldm + r]           = __float2half_rn(c[t][u][0] * scl);
            Ct[(size_t)(n + 1) * ldm + r]     = __float2half_rn(c[t][u][1] * scl);
            Ct[(size_t)n * ldm + r + 8]       = __float2half_rn(c[t][u][2] * scl);
            Ct[(size_t)(n + 1) * ldm + r + 8] = __float2half_rn(c[t][u][3] * scl);
        }
}

// ---------------------------------------------------------------------------
// Fused prepass: ids [0,4096): round x -> fp16.
//                [4096,5120): round Wq/Wk -> fp16 (layout preserved).
//                [5120,6144): transpose+round Wv -> slot 2.
// ---------------------------------------------------------------------------
__global__ __launch_bounds__(256) void prepass_kernel(const float* __restrict__ x,
                                                      const float* __restrict__ Wq,
                                                      const float* __restrict__ Wk,
                                                      const float* __restrict__ Wv) {
    const int id = blockIdx.x;
    if (id < 5120) {
        const float* __restrict__ src;
        __half* __restrict__ dst;
        size_t i;
        if (id < 4096) {
            src = x; dst = g_xh;
            i = (size_t)id * 256 + threadIdx.x;
        } else {
            const int z = (id - 4096) >> 9;
            src = z ? Wk : Wq;
            dst = g_wh + (size_t)z * DM * DM;
            i = (size_t)((id - 4096) & 511) * 256 + threadIdx.x;
        }
        const float4 a = ((const float4*)src)[2 * i];
        const float4 b = ((const float4*)src)[2 * i + 1];
        __half2 h[4] = { __floats2half2_rn(a.x, a.y), __floats2half2_rn(a.z, a.w),
                         __floats2half2_rn(b.x, b.y), __floats2half2_rn(b.z, b.w) };
        ((uint4*)dst)[i] = *(const uint4*)h;
    } else {
        __shared__ float t[32][33];
        __half* __restrict__ O = g_wh + (size_t)2 * DM * DM;
        const int r = id - 5120;
        const int tx = threadIdx.x & 31, ty = threadIdx.x >> 5;
        const int n = (r & 31) * 32 + tx;
        const int k0 = (r >> 5) * 32;
        for (int i = ty; i < 32; i += 8) t[i][tx] = Wv[(size_t)(k0 + i) * DM + n];
        __syncthreads();
        const int ko = (r >> 5) * 32 + tx;
        const int n0 = (r & 31) * 32;
        for (int i = ty; i < 32; i += 8)
            O[(size_t)(n0 + i) * DM + ko] = __float2half_rn(t[tx][i]);
    }
}

// ---------------------------------------------------------------------------
// GEMM 1 (merged): ids [0,64): M = (Wq Wk^T)/32, stored transposed (M^T).
//                  ids [64,576): V-projection -> V^T.
// ---------------------------------------------------------------------------
__global__ __launch_bounds__(256, 2) void mv_kernel() {
    extern __shared__ __half smh[];
    const int id = blockIdx.x;
    float c[2][8][4];
    zero_c(c);

    if (id < 64) {
        const long m0 = (long)(id >> 3) * BM;   // Wq row (d_in_q)
        const long n0 = (long)(id & 7) * BN;    // Wk row (d_in_k)
        const __half* A = g_wh + (size_t)m0 * DM;                    // Wq
        const __half* B = g_wh + (size_t)DM * DM + (size_t)n0 * DM;  // Wk

        gemm_h(smh, A, DM, B, DM, DM / BK, c);

        // g_mth[j][i] = M[i][j] / 32  (fold in the softmax scale exactly)
        epi_store_T(c, g_mth + (size_t)n0 * DM + m0, DM, SCALE);
    } else {
        const int r = id - 64;
        const long n0 = (long)(r & 7) * BN;
        const long m0 = (long)(r >> 3) * BM;
        const __half* A = g_xh + (size_t)m0 * DM;
        const __half* B = g_wh + (size_t)2 * DM * DM + (size_t)n0 * DM;

        gemm_h(smh, A, DM, B, DM, DM / BK, c);

        const int b = (int)(m0 / SEQ);
        const long mloc = m0 - (long)b * SEQ;
        __half* Ct = g_vth + ((size_t)b * DM + n0) * SEQ + mloc;
        epi_store_T(c, Ct, SEQ, 1.0f);
    }
}

// ---------------------------------------------------------------------------
// GEMM 2: T = x @ M  (NT against M^T), fp16 out.
// ---------------------------------------------------------------------------
__global__ __launch_bounds__(256, 2) void t_kernel() {
    extern __shared__ __half smh[];
    const long m0 = (long)(blockIdx.x >> 3) * BM;
    const long n0 = (long)(blockIdx.x & 7) * BN;
    const __half* A = g_xh + (size_t)m0 * DM;
    const __half* B = g_mth + (size_t)n0 * DM;

    float c[2][8][4];
    zero_c(c);
    gemm_h(smh, A, DM, B, DM, DM / BK, c);

    epi_store_h(c, g_th + (size_t)m0 * DM + n0, DM);
}

// ---------------------------------------------------------------------------
// GEMM 3: S = T @ x^T per batch, lower-triangular tiles only, fp16 out
// (pre-scaled logits, in-place buffer shared with probs).
// ---------------------------------------------------------------------------
__global__ __launch_bounds__(256, 2) void score_kernel() {
    extern __shared__ __half smh[];
    const int id = blockIdx.x;
    const int b = id / 136;
    const int tt = id - b * 136;
    int by = (int)((sqrtf(8.0f * tt + 1.0f) - 1.0f) * 0.5f);
    while ((by + 1) * (by + 2) / 2 <= tt) ++by;
    while (by * (by + 1) / 2 > tt) --by;
    const int bx = tt - by * (by + 1) / 2;

    const long m0 = (long)by * BM;
    const long n0 = (long)bx * BN;
    const __half* A = g_th + ((size_t)b * SEQ + m0) * DM;
    const __half* B = g_xh + ((size_t)b * SEQ + n0) * DM;

    float c[2][8][4];
    zero_c(c);
    gemm_h(smh, A, DM, B, DM, DM / BK, c);

    __half* C = g_ph + ((size_t)b * SEQ + m0) * SEQ + n0;
    epi_store_h(c, C, SEQ);
}

// ---------------------------------------------------------------------------
// Softmax (causal, single pass, row in registers, fp16 in place).
// Logits are pre-scaled; zeroes to the 128-tile boundary for PV.
// ---------------------------------------------------------------------------
__global__ __launch_bounds__(256) void softmax_kernel() {
    const int row = blockIdx.x;
    const int b = row >> 11;
    const int q = row & (SEQ - 1);
    __half* __restrict__ P = g_ph + (size_t)b * SEQ * SEQ + (size_t)q * SEQ;
    const int nvalid = q + 1;
    const int nzero = ((q >> 7) + 1) << 7;
    const int tid = threadIdx.x, wid = tid >> 5, lane = tid & 31;

    __shared__ float red[8];

    float v[8];
    float lmax = -CUDART_INF_F;
    #pragma unroll
    for (int j = 0; j < 8; ++j) {
        const int col = j * 256 + tid;
        if (col < nvalid) {
            v[j] = __half2float(P[col]);
            lmax = fmaxf(lmax, v[j]);
        }
    }
    #pragma unroll
    for (int o = 16; o > 0; o >>= 1)
        lmax = fmaxf(lmax, __shfl_xor_sync(0xFFFFFFFFu, lmax, o));
    if (lane == 0) red[wid] = lmax;
    __syncthreads();
    float rmax = red[0];
    #pragma unroll
    for (int w = 1; w < 8; ++w) rmax = fmaxf(rmax, red[w]);
    __syncthreads();

    float lsum = 0.0f;
    #pragma unroll
    for (int j = 0; j < 8; ++j) {
        const int col = j * 256 + tid;
        if (col < nvalid) {
            v[j] = __expf(v[j] - rmax);
            lsum += v[j];
        }
    }
    #pragma unroll
    for (int o = 16; o > 0; o >>= 1)
        lsum += __shfl_xor_sync(0xFFFFFFFFu, lsum, o);
    if (lane == 0) red[wid] = lsum;
    __syncthreads();
    float rsum = red[0];
    #pragma unroll
    for (int w = 1; w < 8; ++w) rsum += red[w];
    const float inv = 1.0f / rsum;

    #pragma unroll
    for (int j = 0; j < 8; ++j) {
        const int col = j * 256 + tid;
        if (col < nzero)
            P[col] = __float2half_rn((col < nvalid) ? v[j] * inv : 0.0f);
    }
}

// ---------------------------------------------------------------------------
// GEMM 4: O = P @ V  (A = P fp16, B = V^T fp16), K truncated at causal edge.
// Heavy tiles first for wave balance.
// ---------------------------------------------------------------------------
__global__ __launch_bounds__(256, 2) void pv_tc_kernel(float* __restrict__ out) {
    extern __shared__ __half smh[];
    const int b = blockIdx.z;
    const long m0 = (long)(gridDim.y - 1 - blockIdx.y) * BM;   // heavy-first
    const long n0 = (long)blockIdx.x * BN;
    const __half* A = g_ph + ((size_t)b * SEQ + m0) * SEQ;
    const __half* B = g_vth + ((size_t)b * DM + n0) * SEQ;
    const int nchunks = (int)((m0 + BM) / BK);

    float c[2][8][4];
    zero_c(c);
    gemm_h(smh, A, SEQ, B, SEQ, nchunks, c);

    float* C = out + ((size_t)b * SEQ + m0) * DM + n0;
    epi_store_f(c, C, DM);
}

// ---------------------------------------------------------------------------
extern "C" void kernel_launch(void* const* d_in, const int* in_sizes, int n_in,
                              void* d_out, int out_size) {
    (void)in_sizes; (void)n_in; (void)out_size;
    const float* x  = (const float*)d_in[0];
    const float* Wq = (const float*)d_in[1];
    const float* Wk = (const float*)d_in[2];
    const float* Wv = (const float*)d_in[3];
    float* out = (float*)d_out;

    cudaFuncSetAttribute(mv_kernel,    cudaFuncAttributeMaxDynamicSharedMemorySize, SMEM_BYTES);
    cudaFuncSetAttribute(t_kernel,     cudaFuncAttributeMaxDynamicSharedMemorySize, SMEM_BYTES);
    cudaFuncSetAttribute(score_kernel, cudaFuncAttributeMaxDynamicSharedMemorySize, SMEM_BYTES);
    cudaFuncSetAttribute(pv_tc_kernel, cudaFuncAttributeMaxDynamicSharedMemorySize, SMEM_BYTES);

    prepass_kernel<<<6144, 256>>>(x, Wq, Wk, Wv);
    mv_kernel<<<576, 256, SMEM_BYTES>>>();           // 64 M + 512 V-proj
    t_kernel<<<512, 256, SMEM_BYTES>>>();            // T = x M
    score_kernel<<<544, 256, SMEM_BYTES>>>();        // triangular S = T x^T
    softmax_kernel<<<BATCH * SEQ, 256>>>();
    {
        dim3 g(DM / BN, SEQ / BM, BATCH);            // 8 x 16 x 4
        pv_tc_kernel<<<g, 256, SMEM_BYTES>>>(out);
    }
}

// round 13
// speedup vs baseline: 8.4740x; 1.0126x over previous
#include <cuda_runtime.h>
#include <cuda_fp16.h>
#include <cstdint>
#include <math_constants.h>

#define BATCH 4
#define SEQ   2048
#define DM    1024
#define MROWS (BATCH * SEQ)
#define SCALE (1.0f / 32.0f)

// GEMM tiling (fp16 operands, fp32 accum)
#define BM 128
#define BN 128
#define BK 64
#define S_H 80                        // row stride in fp16 (64 + 16 pad)
#define TILE_H (BM * S_H)             // 10240 halfs per tile (20480 B)
#define STG_H  (2 * TILE_H)           // A+B per stage
#define SMEM_BYTES (2 * STG_H * 2)    // 81920 B (2 stages)

// Scratch (__device__ globals; allocation-free rule)
__device__ __half g_xh [(size_t)MROWS * DM];         // x   (fp16)
__device__ __half g_wh [(size_t)3 * DM * DM];        // slot0: Wq, slot1: Wk (row-major);
                                                     // slot2: Wv^T
__device__ __half g_mth[(size_t)DM * DM];            // (Wq Wk^T / 32)^T  (fp16)
__device__ __half g_th [(size_t)MROWS * DM];         // T = x (Wq Wk^T / 32)  (fp16)
__device__ __half g_vth[(size_t)MROWS * DM];         // V^T per batch [b][d][key]
__device__ __half g_ph [(size_t)BATCH * SEQ * SEQ];  // scores -> probs (fp16, in place)

// Dataflow counters (reset by prepass each run)
__device__ int g_mcnt;
__device__ int g_tcnt[64];

// ---------------------------------------------------------------------------
__device__ __forceinline__ void cp16(uint32_t dst, const void* src) {
    asm volatile("cp.async.cg.shared.global [%0], [%1], 16;"
                 :: "r"(dst), "l"(src) : "memory");
}

__device__ __forceinline__ void mma16(float* c, const uint32_t* a, const uint32_t* b) {
    asm volatile(
        "mma.sync.aligned.m16n8k16.row.col.f32.f16.f16.f32 "
        "{%0,%1,%2,%3}, {%4,%5,%6,%7}, {%8,%9}, {%0,%1,%2,%3};"
        : "+f"(c[0]), "+f"(c[1]), "+f"(c[2]), "+f"(c[3])
        : "r"(a[0]), "r"(a[1]), "r"(a[2]), "r"(a[3]), "r"(b[0]), "r"(b[1]));
}

// Issue cp.async for a 128x64-fp16 K-major tile into padded SMEM.
__device__ __forceinline__ void load_tile(uint32_t smbase_b, const __half* __restrict__ src,
                                          long ld, int tid) {
    #pragma unroll
    for (int i = 0; i < 4; ++i) {
        int idx = i * 256 + tid;
        int row = idx >> 3, c8 = idx & 7;
        cp16(smbase_b + (uint32_t)(row * (S_H * 2) + c8 * 16),
             src + (size_t)row * ld + c8 * 8);
    }
}

// Load one k16-step of fragments via LDS.64, immediate offsets.
// k-permutation: quad-lane lc reads physical cols 4lc..4lc+3 as logical
// {2lc, 2lc+1, 2lc+8, 2lc+9}; A and B agree, so the k-sum is unchanged.
__device__ __forceinline__ void load_frags(const __half* __restrict__ aP,
                                           const __half* __restrict__ bP,
                                           int ks, uint32_t* a, uint32_t* b) {
    const int k = ks * 16;
    const uint2 u0 = *(const uint2*)(aP + k);               // t=0 row lr
    const uint2 u1 = *(const uint2*)(aP + 8 * S_H + k);     // t=0 row lr+8
    const uint2 u2 = *(const uint2*)(aP + 16 * S_H + k);    // t=1 row lr
    const uint2 u3 = *(const uint2*)(aP + 24 * S_H + k);    // t=1 row lr+8
    a[0] = u0.x; a[1] = u1.x; a[2] = u0.y; a[3] = u1.y;
    a[4] = u2.x; a[5] = u3.x; a[6] = u2.y; a[7] = u3.y;
    #pragma unroll
    for (int u = 0; u < 8; ++u) {
        const uint2 w = *(const uint2*)(bP + u * 8 * S_H + k);
        b[u * 2 + 0] = w.x;
        b[u * 2 + 1] = w.y;
    }
}

// ---------------------------------------------------------------------------
// NT GEMM mainloop: C(128x128,f32) += A(128xK,f16) * B(128xK,f16)^T.
// 2-stage cp.async pipeline, 1 barrier/chunk, k16-level register pipelining.
// ---------------------------------------------------------------------------
__device__ __forceinline__ void gemm_h(__half* sm,
                                       const __half* __restrict__ A, long lda,
                                       const __half* __restrict__ B, long ldb,
                                       int nchunks, float c[2][8][4]) {
    const int tid = threadIdx.x, wid = tid >> 5, lane = tid & 31;
    const int warpM = wid & 3, warpN = wid >> 2;
    const int lr = lane >> 2, lc = lane & 3;
    const uint32_t smu = (uint32_t)__cvta_generic_to_shared(sm);

    const __half* aP0 = sm + (warpM * 32 + lr) * S_H + 4 * lc;
    const __half* bP0 = sm + TILE_H + (warpN * 64 + lr) * S_H + 4 * lc;
    const __half* aP1 = aP0 + STG_H;
    const __half* bP1 = bP0 + STG_H;

    load_tile(smu, A, lda, tid);
    load_tile(smu + TILE_H * 2, B, ldb, tid);
    asm volatile("cp.async.commit_group;" ::: "memory");

    for (int i = 0; i < nchunks; ++i) {
        asm volatile("cp.async.wait_group 0;" ::: "memory");
        __syncthreads();

        const __half* aP = (i & 1) ? aP1 : aP0;
        const __half* bP = (i & 1) ? bP1 : bP0;

        // Critical path first: ks=0 fragments.
        uint32_t aA[8], bA[16], aB[8], bB[16];
        load_frags(aP, bP, 0, aA, bA);

        // Prefetch chunk i+1 (overlaps with MMAs below).
        if (i + 1 < nchunks) {
            const uint32_t s = (uint32_t)((i + 1) & 1) * STG_H * 2;
            load_tile(smu + s, A + (size_t)(i + 1) * BK, lda, tid);
            load_tile(smu + s + TILE_H * 2, B + (size_t)(i + 1) * BK, ldb, tid);
            asm volatile("cp.async.commit_group;" ::: "memory");
        }

        #pragma unroll
        for (int ks = 0; ks < 4; ++ks) {
            if (ks < 3)
                load_frags(aP, bP, ks + 1,
                           (ks & 1) ? aA : aB, (ks & 1) ? bA : bB);
            const uint32_t* a = (ks & 1) ? aB : aA;
            const uint32_t* b = (ks & 1) ? bB : bA;
            #pragma unroll
            for (int t = 0; t < 2; ++t)
                #pragma unroll
                for (int u = 0; u < 8; ++u)
                    mma16(c[t][u], a + t * 4, b + u * 2);
        }
    }
}

__device__ __forceinline__ void zero_c(float c[2][8][4]) {
    #pragma unroll
    for (int t = 0; t < 2; ++t)
        #pragma unroll
        for (int u = 0; u < 8; ++u)
            #pragma unroll
            for (int j = 0; j < 4; ++j) c[t][u][j] = 0.0f;
}

// fp32 row-major epilogue (final output).
__device__ __forceinline__ void epi_store_f(float c[2][8][4], float* __restrict__ C,
                                            long ldc) {
    const int tid = threadIdx.x, wid = tid >> 5, lane = tid & 31;
    const int warpM = wid & 3, warpN = wid >> 2;
    const int lr = lane >> 2, lc = lane & 3;
    #pragma unroll
    for (int t = 0; t < 2; ++t)
        #pragma unroll
        for (int u = 0; u < 8; ++u) {
            const int r = warpM * 32 + t * 16 + lr;
            const int n = warpN * 64 + u * 8 + lc * 2;
            *(float2*)&C[(size_t)r * ldc + n]       = make_float2(c[t][u][0], c[t][u][1]);
            *(float2*)&C[(size_t)(r + 8) * ldc + n] = make_float2(c[t][u][2], c[t][u][3]);
        }
}

// fp16 row-major epilogue (T, scores).
__device__ __forceinline__ void epi_store_h(float c[2][8][4], __half* __restrict__ C,
                                            long ldc) {
    const int tid = threadIdx.x, wid = tid >> 5, lane = tid & 31;
    const int warpM = wid & 3, warpN = wid >> 2;
    const int lr = lane >> 2, lc = lane & 3;
    #pragma unroll
    for (int t = 0; t < 2; ++t)
        #pragma unroll
        for (int u = 0; u < 8; ++u) {
            const int r = warpM * 32 + t * 16 + lr;
            const int n = warpN * 64 + u * 8 + lc * 2;
            *(__half2*)&C[(size_t)r * ldc + n]       = __floats2half2_rn(c[t][u][0], c[t][u][1]);
            *(__half2*)&C[(size_t)(r + 8) * ldc + n] = __floats2half2_rn(c[t][u][2], c[t][u][3]);
        }
}

// fp16 transposed epilogue with scale: Ct[n][m] (for V^T and M^T).
__device__ __forceinline__ void epi_store_T(float c[2][8][4], __half* __restrict__ Ct,
                                            long ldm, float scl) {
    const int tid = threadIdx.x, wid = tid >> 5, lane = tid & 31;
    const int warpM = wid & 3, warpN = wid >> 2;
    const int lr = lane >> 2, lc = lane & 3;
    #pragma unroll
    for (int t = 0; t < 2; ++t)
        #pragma unroll
        for (int u = 0; u < 8; ++u) {
            const int r = warpM * 32 + t * 16 + lr;
            const int n = warpN * 64 + u * 8 + lc * 2;
            Ct[(size_t)n * ldm + r]           = __float2half_rn(c[t][u][0] * scl);
            Ct[(size_t)(n + 1) * ldm + r]     = __float2half_rn(c[t][u][1] * scl);
            Ct[(size_t)n * ldm + r + 8]       = __float2half_rn(c[t][u][2] * scl);
            Ct[(size_t)(n + 1) * ldm + r + 8] = __float2half_rn(c[t][u][3] * scl);
        }
}

// ---------------------------------------------------------------------------
// Spin helpers (producer/consumer across blocks within one kernel).
// ---------------------------------------------------------------------------
__device__ __forceinline__ void signal_done(int* cnt) {
    __threadfence();
    __syncthreads();
    if (threadIdx.x == 0) atomicAdd(cnt, 1);
}

__device__ __forceinline__ void wait_for(const int* cnt, int target) {
    if (threadIdx.x == 0) {
        while (*(volatile const int*)cnt < target) __nanosleep(64);
        __threadfence();
    }
    __syncthreads();
}

// ---------------------------------------------------------------------------
// Fused prepass: ids [0,4096): round x -> fp16.
//                [4096,5120): round Wq/Wk -> fp16 (layout preserved).
//                [5120,6144): transpose+round Wv -> slot 2.
// Block 0 also resets the dataflow counters for this run.
// ---------------------------------------------------------------------------
__global__ __launch_bounds__(256) void prepass_kernel(const float* __restrict__ x,
                                                      const float* __restrict__ Wq,
                                                      const float* __restrict__ Wk,
                                                      const float* __restrict__ Wv) {
    const int id = blockIdx.x;
    if (id == 0) {
        if (threadIdx.x == 0) g_mcnt = 0;
        if (threadIdx.x < 64) g_tcnt[threadIdx.x] = 0;
    }
    if (id < 5120) {
        const float* __restrict__ src;
        __half* __restrict__ dst;
        size_t i;
        if (id < 4096) {
            src = x; dst = g_xh;
            i = (size_t)id * 256 + threadIdx.x;
        } else {
            const int z = (id - 4096) >> 9;
            src = z ? Wk : Wq;
            dst = g_wh + (size_t)z * DM * DM;
            i = (size_t)((id - 4096) & 511) * 256 + threadIdx.x;
        }
        const float4 a = ((const float4*)src)[2 * i];
        const float4 b = ((const float4*)src)[2 * i + 1];
        __half2 h[4] = { __floats2half2_rn(a.x, a.y), __floats2half2_rn(a.z, a.w),
                         __floats2half2_rn(b.x, b.y), __floats2half2_rn(b.z, b.w) };
        ((uint4*)dst)[i] = *(const uint4*)h;
    } else {
        __shared__ float t[32][33];
        __half* __restrict__ O = g_wh + (size_t)2 * DM * DM;
        const int r = id - 5120;
        const int tx = threadIdx.x & 31, ty = threadIdx.x >> 5;
        const int n = (r & 31) * 32 + tx;
        const int k0 = (r >> 5) * 32;
        for (int i = ty; i < 32; i += 8) t[i][tx] = Wv[(size_t)(k0 + i) * DM + n];
        __syncthreads();
        const int ko = (r >> 5) * 32 + tx;
        const int n0 = (r & 31) * 32;
        for (int i = ty; i < 32; i += 8)
            O[(size_t)(n0 + i) * DM + ko] = __float2half_rn(t[tx][i]);
    }
}

// ---------------------------------------------------------------------------
// MEGA kernel: in-kernel dataflow over block-id ranges.
//   [0,64):     M = (Wq Wk^T)/32 -> M^T          (signals g_mcnt)
//   [64,576):   T = x M (waits g_mcnt==64)       (signals g_tcnt[mb])
//   [576,1088): V-projection -> V^T              (independent; fills tails)
//   [1088,1632): S = T x^T triangular tiles      (waits g_tcnt[gb]==8)
// ---------------------------------------------------------------------------
__global__ __launch_bounds__(256, 2) void mega_kernel() {
    extern __shared__ __half smh[];
    const int id = blockIdx.x;
    float c[2][8][4];
    zero_c(c);

    if (id < 64) {
        const long m0 = (long)(id >> 3) * BM;   // Wq row (d_in_q)
        const long n0 = (long)(id & 7) * BN;    // Wk row (d_in_k)
        const __half* A = g_wh + (size_t)m0 * DM;                    // Wq
        const __half* B = g_wh + (size_t)DM * DM + (size_t)n0 * DM;  // Wk

        gemm_h(smh, A, DM, B, DM, DM / BK, c);

        epi_store_T(c, g_mth + (size_t)n0 * DM + m0, DM, SCALE);
        signal_done(&g_mcnt);
    } else if (id < 576) {
        const int r = id - 64;
        const long m0 = (long)(r >> 3) * BM;
        const long n0 = (long)(r & 7) * BN;

        wait_for(&g_mcnt, 64);

        const __half* A = g_xh + (size_t)m0 * DM;
        const __half* B = g_mth + (size_t)n0 * DM;

        gemm_h(smh, A, DM, B, DM, DM / BK, c);

        epi_store_h(c, g_th + (size_t)m0 * DM + n0, DM);
        signal_done(&g_tcnt[r >> 3]);
    } else if (id < 1088) {
        const int r = id - 576;
        const long n0 = (long)(r & 7) * BN;
        const long m0 = (long)(r >> 3) * BM;
        const __half* A = g_xh + (size_t)m0 * DM;
        const __half* B = g_wh + (size_t)2 * DM * DM + (size_t)n0 * DM;

        gemm_h(smh, A, DM, B, DM, DM / BK, c);

        const int b = (int)(m0 / SEQ);
        const long mloc = m0 - (long)b * SEQ;
        __half* Ct = g_vth + ((size_t)b * DM + n0) * SEQ + mloc;
        epi_store_T(c, Ct, SEQ, 1.0f);
    } else {
        const int sid = id - 1088;
        const int b = sid / 136;
        const int tt = sid - b * 136;
        int by = (int)((sqrtf(8.0f * tt + 1.0f) - 1.0f) * 0.5f);
        while ((by + 1) * (by + 2) / 2 <= tt) ++by;
        while (by * (by + 1) / 2 > tt) --by;
        const int bx = tt - by * (by + 1) / 2;

        const long m0 = (long)by * BM;
        const long n0 = (long)bx * BN;
        const int gb = b * 16 + by;

        wait_for(&g_tcnt[gb], 8);

        const __half* A = g_th + ((size_t)b * SEQ + m0) * DM;
        const __half* B = g_xh + ((size_t)b * SEQ + n0) * DM;

        gemm_h(smh, A, DM, B, DM, DM / BK, c);

        __half* C = g_ph + ((size_t)b * SEQ + m0) * SEQ + n0;
        epi_store_h(c, C, SEQ);
    }
}

// ---------------------------------------------------------------------------
// Softmax (causal, single pass, row in registers, fp16 in place).
// Logits are pre-scaled; zeroes to the 128-tile boundary for PV.
// ---------------------------------------------------------------------------
__global__ __launch_bounds__(256) void softmax_kernel() {
    const int row = blockIdx.x;
    const int b = row >> 11;
    const int q = row & (SEQ - 1);
    __half* __restrict__ P = g_ph + (size_t)b * SEQ * SEQ + (size_t)q * SEQ;
    const int nvalid = q + 1;
    const int nzero = ((q >> 7) + 1) << 7;
    const int tid = threadIdx.x, wid = tid >> 5, lane = tid & 31;

    __shared__ float red[8];

    float v[8];
    float lmax = -CUDART_INF_F;
    #pragma unroll
    for (int j = 0; j < 8; ++j) {
        const int col = j * 256 + tid;
        if (col < nvalid) {
            v[j] = __half2float(P[col]);
            lmax = fmaxf(lmax, v[j]);
        }
    }
    #pragma unroll
    for (int o = 16; o > 0; o >>= 1)
        lmax = fmaxf(lmax, __shfl_xor_sync(0xFFFFFFFFu, lmax, o));
    if (lane == 0) red[wid] = lmax;
    __syncthreads();
    float rmax = red[0];
    #pragma unroll
    for (int w = 1; w < 8; ++w) rmax = fmaxf(rmax, red[w]);
    __syncthreads();

    float lsum = 0.0f;
    #pragma unroll
    for (int j = 0; j < 8; ++j) {
        const int col = j * 256 + tid;
        if (col < nvalid) {
            v[j] = __expf(v[j] - rmax);
            lsum += v[j];
        }
    }
    #pragma unroll
    for (int o = 16; o > 0; o >>= 1)
        lsum += __shfl_xor_sync(0xFFFFFFFFu, lsum, o);
    if (lane == 0) red[wid] = lsum;
    __syncthreads();
    float rsum = red[0];
    #pragma unroll
    for (int w = 1; w < 8; ++w) rsum += red[w];
    const float inv = 1.0f / rsum;

    #pragma unroll
    for (int j = 0; j < 8; ++j) {
        const int col = j * 256 + tid;
        if (col < nzero)
            P[col] = __float2half_rn((col < nvalid) ? v[j] * inv : 0.0f);
    }
}

// ---------------------------------------------------------------------------
// GEMM: O = P @ V  (A = P fp16, B = V^T fp16), K truncated at causal edge.
// Heavy tiles first for wave balance.
// ---------------------------------------------------------------------------
__global__ __launch_bounds__(256, 2) void pv_tc_kernel(float* __restrict__ out) {
    extern __shared__ __half smh[];
    const int b = blockIdx.z;
    const long m0 = (long)(gridDim.y - 1 - blockIdx.y) * BM;   // heavy-first
    const long n0 = (long)blockIdx.x * BN;
    const __half* A = g_ph + ((size_t)b * SEQ + m0) * SEQ;
    const __half* B = g_vth + ((size_t)b * DM + n0) * SEQ;
    const int nchunks = (int)((m0 + BM) / BK);

    float c[2][8][4];
    zero_c(c);
    gemm_h(smh, A, SEQ, B, SEQ, nchunks, c);

    float* C = out + ((size_t)b * SEQ + m0) * DM + n0;
    epi_store_f(c, C, DM);
}

// ---------------------------------------------------------------------------
extern "C" void kernel_launch(void* const* d_in, const int* in_sizes, int n_in,
                              void* d_out, int out_size) {
    (void)in_sizes; (void)n_in; (void)out_size;
    const float* x  = (const float*)d_in[0];
    const float* Wq = (const float*)d_in[1];
    const float* Wk = (const float*)d_in[2];
    const float* Wv = (const float*)d_in[3];
    float* out = (float*)d_out;

    cudaFuncSetAttribute(mega_kernel,  cudaFuncAttributeMaxDynamicSharedMemorySize, SMEM_BYTES);
    cudaFuncSetAttribute(pv_tc_kernel, cudaFuncAttributeMaxDynamicSharedMemorySize, SMEM_BYTES);

    prepass_kernel<<<6144, 256>>>(x, Wq, Wk, Wv);
    mega_kernel<<<1632, 256, SMEM_BYTES>>>();        // M -> T -> S with V filling tails
    softmax_kernel<<<BATCH * SEQ, 256>>>();
    {
        dim3 g(DM / BN, SEQ / BM, BATCH);            // 8 x 16 x 4
        pv_tc_kernel<<<g, 256, SMEM_BYTES>>>(out);
    }
}